// round 10
// baseline (speedup 1.0000x reference)
#include <cuda_runtime.h>
#include <math.h>
#include <stdint.h>

#define BATCH 512
#define HID   512
#define NCLS  1000
#define MC    4000
#define INV_SIGMA (1.0f/10.0f)

#if defined(__CUDA_ARCH__) && (__CUDA_ARCH__ == 1030) && defined(__CUDA_ARCH_FEAT_SM103_ALL)
#define HAS_TC 1
#else
#define HAS_TC 0
#endif

// ---------------- scratch ----------------
__device__ __align__(16) float g_a[4096];        // ||w_m||^2 (exact fp32)
__device__ __align__(16) float g_fsq[BATCH];     // ||f_b||^2
__device__ __align__(16) float g_s[HID];         // col sums of W (from rounded Wt)
__device__ __align__(16) float g_u[HID];         // u_k = sum_m a_m Wt[k,m]
__device__ __align__(16) float g_Wt[512*4096];   // W^T, tf32-RN-rounded, stride 4096
// Gram partials: 10 (ti<=tj) tiles x 5 m-chunks x 128x128
__device__ __align__(16) float g_G2[10*5*16384];
__device__ double g_f2p[128];                    // F2 partials (116 used)

__constant__ int c_ti[10] = {0,0,0,0,1,1,1,2,2,3};
__constant__ int c_tj[10] = {0,1,2,3,1,2,3,2,3,3};

// ---------------- PTX helpers ----------------
__device__ __forceinline__ uint32_t smem_u32(const void* p) {
    uint32_t a;
    asm("{ .reg .u64 t; cvta.to.shared.u64 t, %1; cvt.u32.u64 %0, t; }"
        : "=r"(a) : "l"(p));
    return a;
}
__device__ __forceinline__ uint32_t elect_one() {
    uint32_t pred;
    asm volatile("{\n\t.reg .pred p;\n\telect.sync _|p, 0xFFFFFFFF;\n\t"
                 "selp.b32 %0, 1, 0, p;\n\t}" : "=r"(pred));
    return pred;
}
__device__ __forceinline__ float tf32_rn(float x) {
    float r;
    asm("cvt.rna.tf32.f32 %0, %1;" : "=f"(r) : "f"(x));
    return r;
}
#define MBAR_INIT(addr, cnt) \
    asm volatile("mbarrier.init.shared.b64 [%0], %1;" :: "r"(addr), "r"(cnt) : "memory")
#define MBAR_WAIT(addr, par) do { \
    uint32_t _m = (addr), _p = (par), _d; \
    asm volatile("{\n\t.reg .pred p;\n\t" \
        "mbarrier.try_wait.parity.acquire.cta.shared::cta.b64 p, [%1], %2;\n\t" \
        "selp.b32 %0, 1, 0, p;\n\t}" : "=r"(_d) : "r"(_m), "r"(_p) : "memory"); \
    if (!_d) { \
        asm volatile("{\n\t.reg .pred P1;\n\tWL%=:\n\t" \
            "mbarrier.try_wait.parity.acquire.cta.shared::cta.b64 P1, [%0], %1, 0x989680;\n\t" \
            "@P1 bra.uni WD%=;\n\tbra.uni WL%=;\n\tWD%=:\n\t}" \
            :: "r"(_m), "r"(_p) : "memory"); \
    } } while (0)

#if HAS_TC
#define TC_ALLOC(smem_addr, n) \
    asm volatile("tcgen05.alloc.cta_group::1.sync.aligned.shared::cta.b32 [%0], %1;" \
        :: "r"(smem_addr), "r"(n) : "memory")
#define TC_DEALLOC(tmem, n) \
    asm volatile("tcgen05.dealloc.cta_group::1.sync.aligned.b32 %0, %1;" :: "r"(tmem), "r"(n))
#define TC_RELINQ() \
    asm volatile("tcgen05.relinquish_alloc_permit.cta_group::1.sync.aligned;")
#define TC_COMMIT(mbar) \
    asm volatile("tcgen05.commit.cta_group::1.mbarrier::arrive::one.shared::cluster.b64 [%0];" \
        :: "r"(mbar) : "memory")
#define TC_FENCE_AFTER() asm volatile("tcgen05.fence::after_thread_sync;" ::: "memory")
#define TC_FENCE_BEFORE() asm volatile("tcgen05.fence::before_thread_sync;" ::: "memory")
#define TC_WAIT_LD() asm volatile("tcgen05.wait::ld.sync.aligned;" ::: "memory")
#define LDTM_X32(r, addr) \
    asm volatile("tcgen05.ld.sync.aligned.32x32b.x32.b32 " \
        "{%0,%1,%2,%3,%4,%5,%6,%7,%8,%9,%10,%11,%12,%13,%14,%15," \
        "%16,%17,%18,%19,%20,%21,%22,%23,%24,%25,%26,%27,%28,%29,%30,%31}, [%32];" \
        : "=r"((r)[0]),"=r"((r)[1]),"=r"((r)[2]),"=r"((r)[3]), \
          "=r"((r)[4]),"=r"((r)[5]),"=r"((r)[6]),"=r"((r)[7]), \
          "=r"((r)[8]),"=r"((r)[9]),"=r"((r)[10]),"=r"((r)[11]), \
          "=r"((r)[12]),"=r"((r)[13]),"=r"((r)[14]),"=r"((r)[15]), \
          "=r"((r)[16]),"=r"((r)[17]),"=r"((r)[18]),"=r"((r)[19]), \
          "=r"((r)[20]),"=r"((r)[21]),"=r"((r)[22]),"=r"((r)[23]), \
          "=r"((r)[24]),"=r"((r)[25]),"=r"((r)[26]),"=r"((r)[27]), \
          "=r"((r)[28]),"=r"((r)[29]),"=r"((r)[30]),"=r"((r)[31]) \
        : "r"(addr))

// SW128 K-major desc: LBO=1, SBO=64, version=1, layout=2
static __device__ __forceinline__ uint64_t make_desc(uint32_t addr) {
    const uint64_t base = (uint64_t(2) << 61) | (uint64_t(1) << 46)
                        | (uint64_t(64) << 32) | (uint64_t(1) << 16);
    return base | ((uint64_t)(addr >> 4) & 0x3FFF);
}
// tf32 SS MMA, cg1: D[128,128] += A[128,8] * B[128,8]^T
__device__ __forceinline__ void mma_tf32(uint32_t d, uint64_t ad, uint64_t bd,
                                         uint32_t idesc, uint32_t en) {
    asm volatile("{\n\t.reg .pred p;\n\tsetp.ne.u32 p, %5, 0;\n\t"
        "tcgen05.mma.cta_group::1.kind::tf32 [%0], %1, %2, %3, {%4,%4,%4,%4}, p;\n\t}"
        :: "r"(d), "l"(ad), "l"(bd), "r"(idesc), "r"(0u), "r"(en) : "memory");
}
#endif  // HAS_TC

__device__ __forceinline__ uint32_t swz(uint32_t o) { return o ^ ((o >> 3) & 0x70); }

__device__ __forceinline__ void cp16(uint32_t dst, const void* src, bool valid) {
    int sz = valid ? 16 : 0;
    asm volatile("cp.async.cg.shared.global [%0], [%1], 16, %2;"
                 :: "r"(dst), "l"(src), "r"(sz));
}

// ---------------- pipeline layout (shared by both tcgen05 GEMMs) ----------------
#define STG       4
#define STG_BYTES 16384     // 128 rows x 128B
#define OFF_A     1024
#define OFF_B     (1024 + STG*STG_BYTES)
#define SMEM_TC   (1024 + 2*STG*STG_BYTES)
// idesc: cF32 | aTF32 | bTF32 | N=128 | M=128
#define IDESC_TF32 ((1u<<4) | (2u<<7) | (2u<<10) | (16u<<17) | (8u<<24))

// ================= STAGE A: transpose (blocks 0..1999) || pre (2000..2140) ======
__global__ void __launch_bounds__(256) k_stageA(const float* __restrict__ W,
                                                const float* __restrict__ F) {
    __shared__ float tile[32][33];
    int tid = threadIdx.x;
    if (blockIdx.x < 2000) {
        // transpose + tf32-RN round: Wt[k][m] = rn(W[m][k])
        int k0 = (blockIdx.x & 15) * 32, m0 = (blockIdx.x >> 4) * 32;
        int x = tid & 31, y = tid >> 5;
        #pragma unroll
        for (int i = 0; i < 4; i++)
            tile[y + i * 8][x] = W[(size_t)(m0 + y + i * 8) * HID + k0 + x];
        __syncthreads();
        #pragma unroll
        for (int i = 0; i < 4; i++)
            g_Wt[(size_t)(k0 + y + i * 8) * 4096 + m0 + x] = tf32_rn(tile[x][y + i * 8]);
    } else {
        // pre: a_m = ||w_m||^2 (4 rows/warp, loads batched up-front); fsq
        int warp = ((blockIdx.x - 2000) * 256 + tid) >> 5;   // 0..1127
        int lane = tid & 31;
        int r0 = warp * 4;
        bool isW = (r0 < MC);
        const float* base = isW ? W : F;
        int rb = isW ? r0 : (r0 - MC);
        float4 v[4][4];
        #pragma unroll
        for (int j = 0; j < 4; j++)
            #pragma unroll
            for (int q = 0; q < 4; q++)
                v[j][q] = reinterpret_cast<const float4*>(
                    base + (size_t)(rb + j) * HID)[lane + q * 32];
        float acc[4];
        #pragma unroll
        for (int j = 0; j < 4; j++) {
            float a = 0.f;
            #pragma unroll
            for (int q = 0; q < 4; q++)
                a += v[j][q].x*v[j][q].x + v[j][q].y*v[j][q].y
                   + v[j][q].z*v[j][q].z + v[j][q].w*v[j][q].w;
            acc[j] = a;
        }
        #pragma unroll
        for (int o = 16; o > 0; o >>= 1)
            #pragma unroll
            for (int j = 0; j < 4; j++)
                acc[j] += __shfl_down_sync(0xffffffffu, acc[j], o);
        if (lane == 0) {
            #pragma unroll
            for (int j = 0; j < 4; j++) {
                if (isW) g_a[r0 + j] = acc[j];
                else     g_fsq[rb + j] = acc[j];
            }
        }
    }
}

// ================= STAGE B: gram (blocks 0..49) || fw (50..177) =================
#define GK_NCHUNK 25
#define KC      32
#define NCHUNK  16

#if HAS_TC
__device__ __forceinline__ void gram_load_chunk(uint32_t sb, int stage, int c,
                                                int K0, int L0, int mbase, int tid) {
    int moff = mbase + c * 32;
    uint32_t dA = sb + OFF_A + stage * STG_BYTES;
    uint32_t dB = sb + OFF_B + stage * STG_BYTES;
    #pragma unroll
    for (int p = 0; p < 8; p++) {
        int idx = p * 128 + tid;
        int r = idx >> 3, seg = idx & 7;
        uint32_t off = swz((uint32_t)(r * 128 + seg * 16));
        cp16(dA + off, g_Wt + (size_t)(K0 + r) * 4096 + moff + seg * 4, true);
        cp16(dB + off, g_Wt + (size_t)(L0 + r) * 4096 + moff + seg * 4, true);
    }
}
__device__ __forceinline__ void fw_load_chunk(uint32_t sb, int stage, int c,
                                              const float* __restrict__ W,
                                              const float* __restrict__ F,
                                              int m0, int b0, int tid) {
    int kc = c * KC;
    uint32_t dA = sb + OFF_A + stage * STG_BYTES;
    uint32_t dB = sb + OFF_B + stage * STG_BYTES;
    #pragma unroll
    for (int p = 0; p < 8; p++) {
        int idx = p * 128 + tid;
        int r = idx >> 3, seg = idx & 7;
        uint32_t off = swz((uint32_t)(r * 128 + seg * 16));
        int m = m0 + r;
        bool v = (m < MC);
        cp16(dA + off, W + (size_t)(v ? m : 0) * HID + kc + seg * 4, v);
        cp16(dB + off, F + (size_t)(b0 + r) * HID + kc + seg * 4, true);
    }
}
#endif

__global__ void __launch_bounds__(128, 1) k_stageB(const float* __restrict__ F,
                                                   const float* __restrict__ W,
                                                   float* __restrict__ out) {
    int tid = threadIdx.x, wid = tid >> 5, lane = tid & 31;
#if HAS_TC
    extern __shared__ char smem[];
    uint32_t sb = smem_u32(smem);

    if (tid < 4) MBAR_INIT(sb + tid * 8, 1);
    if (wid == 0) { TC_ALLOC(sb + 32, 128); TC_RELINQ(); }
    __syncthreads();
    uint32_t tmem;
    asm volatile("ld.shared.b32 %0, [%1];" : "=r"(tmem) : "r"(sb + 32));

    if (blockIdx.x < 50) {
        // ---- gram: G = Wt . Wt^T ----
        int t = blockIdx.x / 5, z = blockIdx.x % 5;
        int K0 = c_ti[t] * 128, L0 = c_tj[t] * 128, mbase = z * 800;

        #pragma unroll
        for (int c0 = 0; c0 < 3; c0++) {
            gram_load_chunk(sb, c0, c0, K0, L0, mbase, tid);
            asm volatile("cp.async.commit_group;" ::: "memory");
        }
        uint32_t phv = 0;
        for (int c = 0; c < GK_NCHUNK; c++) {
            int s = c & 3;
            if (c + 3 < GK_NCHUNK) {
                int so = (c + 3) & 3;
                if (c >= 1) {
                    MBAR_WAIT(sb + so * 8, (phv >> so) & 1u);
                    phv ^= (1u << so);
                }
                gram_load_chunk(sb, so, c + 3, K0, L0, mbase, tid);
            }
            asm volatile("cp.async.commit_group;" ::: "memory");
            asm volatile("cp.async.wait_group 3;" ::: "memory");
            __syncthreads();
            if (wid == 0 && elect_one()) {
                asm volatile("fence.proxy.async.shared::cta;" ::: "memory");
                uint64_t ad = make_desc(sb + OFF_A + s * STG_BYTES);
                uint64_t bd = make_desc(sb + OFF_B + s * STG_BYTES);
                #pragma unroll
                for (int k = 0; k < 4; k++)
                    mma_tf32(tmem, ad + k * 2, bd + k * 2, IDESC_TF32,
                             (c > 0 || k > 0) ? 1u : 0u);
                TC_COMMIT(sb + s * 8);
            }
        }
        __syncthreads();
        {
            int so = (GK_NCHUNK - 1) & 3;
            MBAR_WAIT(sb + so * 8, (phv >> so) & 1u);
        }
        TC_FENCE_AFTER();

        float* dst = g_G2 + ((size_t)blockIdx.x << 14);
        int row = wid * 32 + lane;
        #pragma unroll
        for (int j0 = 0; j0 < 128; j0 += 32) {
            uint32_t r[32];
            LDTM_X32(r, tmem + j0);
            TC_WAIT_LD();
            #pragma unroll
            for (int j4 = 0; j4 < 8; j4++) {
                float4 v = make_float4(__uint_as_float(r[j4*4+0]), __uint_as_float(r[j4*4+1]),
                                       __uint_as_float(r[j4*4+2]), __uint_as_float(r[j4*4+3]));
                *reinterpret_cast<float4*>(&dst[(size_t)row * 128 + j0 + j4 * 4]) = v;
            }
        }
    } else {
        // ---- fw: tcgen05 GEMM + fused distance epilogue ----
        int fwid = (int)blockIdx.x - 50;
        int m0 = (fwid & 31) * 128, b0 = (fwid >> 5) * 128;

        #pragma unroll
        for (int c0 = 0; c0 < 3; c0++) {
            fw_load_chunk(sb, c0, c0, W, F, m0, b0, tid);
            asm volatile("cp.async.commit_group;" ::: "memory");
        }
        uint32_t phv = 0;
        for (int c = 0; c < NCHUNK; c++) {
            int s = c & 3;
            if (c + 3 < NCHUNK) {
                int so = (c + 3) & 3;
                if (c >= 1) {
                    MBAR_WAIT(sb + so * 8, (phv >> so) & 1u);
                    phv ^= (1u << so);
                }
                fw_load_chunk(sb, so, c + 3, W, F, m0, b0, tid);
            }
            asm volatile("cp.async.commit_group;" ::: "memory");
            asm volatile("cp.async.wait_group 3;" ::: "memory");
            __syncthreads();
            if (wid == 0 && elect_one()) {
                asm volatile("fence.proxy.async.shared::cta;" ::: "memory");
                uint64_t ad = make_desc(sb + OFF_A + s * STG_BYTES);
                uint64_t bd = make_desc(sb + OFF_B + s * STG_BYTES);
                #pragma unroll
                for (int k = 0; k < 4; k++)
                    mma_tf32(tmem, ad + k * 2, bd + k * 2, IDESC_TF32,
                             (c > 0 || k > 0) ? 1u : 0u);
                TC_COMMIT(sb + s * 8);
            }
        }
        __syncthreads();
        MBAR_WAIT(sb + 3 * 8, (phv >> 3) & 1u);
        TC_FENCE_AFTER();

        int m = m0 + wid * 32 + lane;
        float a = (m < MC) ? __ldg(&g_a[m]) : __int_as_float(0x7f800000);
        int grp = m >> 2;
        #pragma unroll
        for (int j0 = 0; j0 < 128; j0 += 32) {
            uint32_t r[32];
            LDTM_X32(r, tmem + j0);
            TC_WAIT_LD();
            #pragma unroll
            for (int jj = 0; jj < 32; jj++) {
                float fw = __uint_as_float(r[jj]);
                float x = fmaf(-2.f, fw, a);
                x = fminf(x, __shfl_xor_sync(0xffffffffu, x, 1));
                x = fminf(x, __shfl_xor_sync(0xffffffffu, x, 2));
                if ((lane & 3) == 0 && m < MC) {
                    int b = b0 + j0 + jj;
                    out[(size_t)b * (NCLS + 1) + grp] =
                        expf(-(__ldg(&g_fsq[b]) + x) * INV_SIGMA);
                }
            }
        }
    }
    TC_FENCE_BEFORE();
    __syncthreads();
    if (wid == 0) TC_DEALLOC(tmem, 128);
#else
    // correct fallback (never selected on GB300)
    if (blockIdx.x < 50) {
        int t = blockIdx.x / 5, z = blockIdx.x % 5;
        int K0 = c_ti[t] * 128, L0 = c_tj[t] * 128, mbase = z * 800;
        float* dst = g_G2 + ((size_t)blockIdx.x << 14);
        for (int e = tid; e < 16384; e += blockDim.x) {
            int k = K0 + (e >> 7), l = L0 + (e & 127);
            float acc = 0.f;
            for (int m = 0; m < 800; m++)
                acc = fmaf(g_Wt[(size_t)k * 4096 + mbase + m],
                           g_Wt[(size_t)l * 4096 + mbase + m], acc);
            dst[e] = acc;
        }
    } else {
        int fwid = (int)blockIdx.x - 50;
        int m0 = (fwid & 31) * 128, b0 = (fwid >> 5) * 128;
        int m = m0 + tid;
        if (m >= MC) return;
        float a = g_a[m];
        int grp = m >> 2;
        const float* wrow = W + (size_t)m * HID;
        for (int jb = 0; jb < 128; jb++) {
            int b = b0 + jb;
            const float* frow = F + (size_t)b * HID;
            float dot = 0.f;
            for (int k = 0; k < HID; k++) dot = fmaf(wrow[k], frow[k], dot);
            float x = fmaf(-2.f, dot, a);
            x = fminf(x, __shfl_xor_sync(0xffffffffu, x, 1));
            x = fminf(x, __shfl_xor_sync(0xffffffffu, x, 2));
            if ((tid & 3) == 0)
                out[(size_t)b * (NCLS + 1) + grp] =
                    expf(-(g_fsq[b] + x) * INV_SIGMA);
        }
    }
#endif
}

// ================= STAGE C: f2 (blocks 0..115) || su (116..147) =================
__global__ void __launch_bounds__(128) k_stageC() {
    int tid = threadIdx.x, wid = tid >> 5, lane = tid & 31;
    if (blockIdx.x < 116) {
        // ---- f2 partial ----
        double acc = 0.0;
        for (int i = (int)blockIdx.x * 128 + tid; i < 10 * 16384; i += 116 * 128) {
            int t = i >> 14, e = i & 16383;
            float g = 0.f;
            #pragma unroll
            for (int z = 0; z < 5; z++) g += g_G2[((size_t)(t * 5 + z) << 14) + e];
            double w = (c_ti[t] == c_tj[t]) ? 1.0 : 2.0;
            acc += w * (double)g * (double)g;
        }
        __shared__ double sd[128];
        sd[tid] = acc;
        __syncthreads();
        for (int o = 64; o > 0; o >>= 1) {
            if (tid < o) sd[tid] += sd[tid + o];
            __syncthreads();
        }
        if (tid == 0) g_f2p[blockIdx.x] = sd[0];
    } else {
        // ---- su: s_k, u_k ; 32 blocks x 4 warps x 4 k ----
        int kb = ((int)blockIdx.x - 116) * 16 + wid * 4;
        #pragma unroll
        for (int j = 0; j < 4; j++) {
            int k = kb + j;
            const float4* row = reinterpret_cast<const float4*>(g_Wt + (size_t)k * 4096);
            const float4* av  = reinterpret_cast<const float4*>(g_a);
            float s = 0.f, u = 0.f;
            #pragma unroll 8
            for (int q = 0; q < 32; q++) {
                int i4 = lane + q * 32;
                if (i4 < 1000) {
                    float4 w = row[i4];
                    float4 a = av[i4];
                    s += w.x + w.y + w.z + w.w;
                    u += a.x*w.x + a.y*w.y + a.z*w.z + a.w*w.w;
                }
            }
            #pragma unroll
            for (int o = 16; o > 0; o >>= 1) {
                s += __shfl_down_sync(0xffffffffu, s, o);
                u += __shfl_down_sync(0xffffffffu, u, o);
            }
            if (lane == 0) { g_s[k] = s; g_u[k] = u; }
        }
    }
}

// ---------------- finalize: fp64 warp-shfl reductions + rw column ----------------
__global__ void k_finalize(float* __restrict__ out) {
    __shared__ double sw[16][5];
    __shared__ float rw_s;
    int t = threadIdx.x, wid = t >> 5, lane = t & 31;

    double la = 0.0, la2 = 0.0;
    {
        const float4* av = reinterpret_cast<const float4*>(g_a);
        float4 v0 = av[t * 2], v1 = av[t * 2 + 1];     // t*8 .. t*8+7 < 4096
        // indices >= MC are never written; rely on explicit mask
        int base = t * 8;
        float e[8] = {v0.x,v0.y,v0.z,v0.w,v1.x,v1.y,v1.z,v1.w};
        #pragma unroll
        for (int i = 0; i < 8; i++)
            if (base + i < MC) { double a = (double)e[i]; la += a; la2 += a * a; }
    }
    double ls2 = (double)g_s[t] * (double)g_s[t];
    double lat = (double)g_u[t] * (double)g_s[t];
    double lf2 = (t < 116) ? g_f2p[t] : 0.0;

    double r[5] = {la, la2, ls2, lat, lf2};
    #pragma unroll
    for (int q = 0; q < 5; q++)
        #pragma unroll
        for (int o = 16; o > 0; o >>= 1)
            r[q] += __shfl_down_sync(0xffffffffu, r[q], o);
    if (lane == 0)
        #pragma unroll
        for (int q = 0; q < 5; q++) sw[wid][q] = r[q];
    __syncthreads();

    if (wid == 0) {
        double v[5];
        #pragma unroll
        for (int q = 0; q < 5; q++) v[q] = (lane < 16) ? sw[lane][q] : 0.0;
        #pragma unroll
        for (int q = 0; q < 5; q++)
            #pragma unroll
            for (int o = 8; o > 0; o >>= 1)
                v[q] += __shfl_down_sync(0xffffffffu, v[q], o);
        if (lane == 0) {
            double sum_a = v[0], sum_a2 = v[1], s2 = v[2], sum_at = v[3], F2 = v[4];
            double mc = (double)MC;
            double denom = 2.0 / (mc * mc - mc);
            double S1 = mc * sum_a - s2;
            double mu = denom * S1;
            double S2 = mc * sum_a2 + sum_a * sum_a + 2.0 * F2 - 4.0 * sum_at;
            rw_s = (float)(denom * S2 - mu * mu);
        }
    }
    __syncthreads();
    out[(size_t)t * (NCLS + 1) + NCLS] = rw_s;
}

extern "C" void kernel_launch(void* const* d_in, const int* in_sizes, int n_in,
                              void* d_out, int out_size) {
    const float* F = (const float*)d_in[0];   // [512,512]
    const float* W = (const float*)d_in[1];   // [4000,512]
    float* out = (float*)d_out;               // [512,1001]
    (void)in_sizes; (void)n_in; (void)out_size;

    static bool inited = false;
    if (!inited) {
        cudaFuncSetAttribute(k_stageB, cudaFuncAttributeMaxDynamicSharedMemorySize,
                             SMEM_TC);
        inited = true;
    }

    k_stageA<<<2141, 256>>>(W, F);               // transpose || pre
    k_stageB<<<178, 128, SMEM_TC>>>(F, W, out);  // gram || fw (independent chains)
    k_stageC<<<148, 128>>>();                    // f2 || su
    k_finalize<<<1, 512>>>(out);
}

// round 11
// speedup vs baseline: 1.3592x; 1.3592x over previous
#include <cuda_runtime.h>
#include <math.h>
#include <stdint.h>

#define BATCH 512
#define HID   512
#define NCLS  1000
#define MC    4000
#define INV_SIGMA (1.0f/10.0f)

#if defined(__CUDA_ARCH__) && (__CUDA_ARCH__ == 1030) && defined(__CUDA_ARCH_FEAT_SM103_ALL)
#define HAS_TC 1
#else
#define HAS_TC 0
#endif

// ---------------- scratch ----------------
__device__ __align__(16) float g_a[4096];        // ||w_m||^2 (exact fp32)
__device__ __align__(16) float g_fsq[BATCH];     // ||f_b||^2
__device__ __align__(16) float g_Wt[512*4096];   // W^T, tf32-RN-rounded, stride 4096
__device__ __align__(16) float g_G2[10*5*16384]; // Gram partials
__device__ double g_ap[141], g_a2p[141];         // per-block sum a, sum a^2
__device__ double g_s2p[64], g_usp[64];          // per-block sum s^2, sum u*s
__device__ double g_f2p[160];                    // per-block F2 partials
__device__ unsigned g_ctr = 0;                   // arrival counter (reset each run)

__constant__ int c_ti[10] = {0,0,0,0,1,1,1,2,2,3};
__constant__ int c_tj[10] = {0,1,2,3,1,2,3,2,3,3};

// ---------------- PTX helpers ----------------
__device__ __forceinline__ uint32_t smem_u32(const void* p) {
    uint32_t a;
    asm("{ .reg .u64 t; cvta.to.shared.u64 t, %1; cvt.u32.u64 %0, t; }"
        : "=r"(a) : "l"(p));
    return a;
}
__device__ __forceinline__ uint32_t elect_one() {
    uint32_t pred;
    asm volatile("{\n\t.reg .pred p;\n\telect.sync _|p, 0xFFFFFFFF;\n\t"
                 "selp.b32 %0, 1, 0, p;\n\t}" : "=r"(pred));
    return pred;
}
__device__ __forceinline__ float tf32_rn(float x) {
    float r;
    asm("cvt.rna.tf32.f32 %0, %1;" : "=f"(r) : "f"(x));
    return r;
}
#define MBAR_INIT(addr, cnt) \
    asm volatile("mbarrier.init.shared.b64 [%0], %1;" :: "r"(addr), "r"(cnt) : "memory")
#define MBAR_WAIT(addr, par) do { \
    uint32_t _m = (addr), _p = (par), _d; \
    asm volatile("{\n\t.reg .pred p;\n\t" \
        "mbarrier.try_wait.parity.acquire.cta.shared::cta.b64 p, [%1], %2;\n\t" \
        "selp.b32 %0, 1, 0, p;\n\t}" : "=r"(_d) : "r"(_m), "r"(_p) : "memory"); \
    if (!_d) { \
        asm volatile("{\n\t.reg .pred P1;\n\tWL%=:\n\t" \
            "mbarrier.try_wait.parity.acquire.cta.shared::cta.b64 P1, [%0], %1, 0x989680;\n\t" \
            "@P1 bra.uni WD%=;\n\tbra.uni WL%=;\n\tWD%=:\n\t}" \
            :: "r"(_m), "r"(_p) : "memory"); \
    } } while (0)

#if HAS_TC
#define TC_ALLOC(smem_addr, n) \
    asm volatile("tcgen05.alloc.cta_group::1.sync.aligned.shared::cta.b32 [%0], %1;" \
        :: "r"(smem_addr), "r"(n) : "memory")
#define TC_DEALLOC(tmem, n) \
    asm volatile("tcgen05.dealloc.cta_group::1.sync.aligned.b32 %0, %1;" :: "r"(tmem), "r"(n))
#define TC_RELINQ() \
    asm volatile("tcgen05.relinquish_alloc_permit.cta_group::1.sync.aligned;")
#define TC_COMMIT(mbar) \
    asm volatile("tcgen05.commit.cta_group::1.mbarrier::arrive::one.shared::cluster.b64 [%0];" \
        :: "r"(mbar) : "memory")
#define TC_FENCE_AFTER() asm volatile("tcgen05.fence::after_thread_sync;" ::: "memory")
#define TC_FENCE_BEFORE() asm volatile("tcgen05.fence::before_thread_sync;" ::: "memory")
#define TC_WAIT_LD() asm volatile("tcgen05.wait::ld.sync.aligned;" ::: "memory")
#define LDTM_X32(r, addr) \
    asm volatile("tcgen05.ld.sync.aligned.32x32b.x32.b32 " \
        "{%0,%1,%2,%3,%4,%5,%6,%7,%8,%9,%10,%11,%12,%13,%14,%15," \
        "%16,%17,%18,%19,%20,%21,%22,%23,%24,%25,%26,%27,%28,%29,%30,%31}, [%32];" \
        : "=r"((r)[0]),"=r"((r)[1]),"=r"((r)[2]),"=r"((r)[3]), \
          "=r"((r)[4]),"=r"((r)[5]),"=r"((r)[6]),"=r"((r)[7]), \
          "=r"((r)[8]),"=r"((r)[9]),"=r"((r)[10]),"=r"((r)[11]), \
          "=r"((r)[12]),"=r"((r)[13]),"=r"((r)[14]),"=r"((r)[15]), \
          "=r"((r)[16]),"=r"((r)[17]),"=r"((r)[18]),"=r"((r)[19]), \
          "=r"((r)[20]),"=r"((r)[21]),"=r"((r)[22]),"=r"((r)[23]), \
          "=r"((r)[24]),"=r"((r)[25]),"=r"((r)[26]),"=r"((r)[27]), \
          "=r"((r)[28]),"=r"((r)[29]),"=r"((r)[30]),"=r"((r)[31]) \
        : "r"(addr))

static __device__ __forceinline__ uint64_t make_desc(uint32_t addr) {
    const uint64_t base = (uint64_t(2) << 61) | (uint64_t(1) << 46)
                        | (uint64_t(64) << 32) | (uint64_t(1) << 16);
    return base | ((uint64_t)(addr >> 4) & 0x3FFF);
}
__device__ __forceinline__ void mma_tf32(uint32_t d, uint64_t ad, uint64_t bd,
                                         uint32_t idesc, uint32_t en) {
    asm volatile("{\n\t.reg .pred p;\n\tsetp.ne.u32 p, %5, 0;\n\t"
        "tcgen05.mma.cta_group::1.kind::tf32 [%0], %1, %2, %3, {%4,%4,%4,%4}, p;\n\t}"
        :: "r"(d), "l"(ad), "l"(bd), "r"(idesc), "r"(0u), "r"(en) : "memory");
}
#endif  // HAS_TC

__device__ __forceinline__ uint32_t swz(uint32_t o) { return o ^ ((o >> 3) & 0x70); }

__device__ __forceinline__ void cp16(uint32_t dst, const void* src, bool valid) {
    int sz = valid ? 16 : 0;
    asm volatile("cp.async.cg.shared.global [%0], [%1], 16, %2;"
                 :: "r"(dst), "l"(src), "r"(sz));
}

// ---------------- transpose + tf32-RN round ----------------
__global__ void __launch_bounds__(256) k_transpose(const float* __restrict__ W) {
    __shared__ float tile[32][33];
    int k0 = (blockIdx.x & 15) * 32, m0 = (blockIdx.x >> 4) * 32;
    int x = threadIdx.x & 31, y = threadIdx.x >> 5;
    #pragma unroll
    for (int i = 0; i < 4; i++)
        tile[y + i * 8][x] = W[(size_t)(m0 + y + i * 8) * HID + k0 + x];
    __syncthreads();
    #pragma unroll
    for (int i = 0; i < 4; i++)
        g_Wt[(size_t)(k0 + y + i * 8) * 4096 + m0 + x] = tf32_rn(tile[x][y + i * 8]);
}

// ---------------- pre: a_m, fsq + per-block fp64 (sum a, sum a^2) ----------------
// 141 blocks x 256 (8 warps x 4 rows)
__global__ void __launch_bounds__(256) k_pre(const float* __restrict__ W,
                                             const float* __restrict__ F) {
    __shared__ double sda[8], sda2[8];
    int tid = threadIdx.x, wid = tid >> 5, lane = tid & 31;
    int warp = (int)blockIdx.x * 8 + wid;
    int r0 = warp * 4;
    bool isW = (r0 < MC);
    const float* base = isW ? W : F;
    int rb = isW ? r0 : (r0 - MC);
    float4 v[4][4];
    #pragma unroll
    for (int j = 0; j < 4; j++)
        #pragma unroll
        for (int q = 0; q < 4; q++)
            v[j][q] = reinterpret_cast<const float4*>(
                base + (size_t)(rb + j) * HID)[lane + q * 32];
    float acc[4];
    #pragma unroll
    for (int j = 0; j < 4; j++) {
        float a = 0.f;
        #pragma unroll
        for (int q = 0; q < 4; q++)
            a += v[j][q].x*v[j][q].x + v[j][q].y*v[j][q].y
               + v[j][q].z*v[j][q].z + v[j][q].w*v[j][q].w;
        acc[j] = a;
    }
    #pragma unroll
    for (int o = 16; o > 0; o >>= 1)
        #pragma unroll
        for (int j = 0; j < 4; j++)
            acc[j] += __shfl_down_sync(0xffffffffu, acc[j], o);
    if (lane == 0) {
        double da = 0.0, da2 = 0.0;
        #pragma unroll
        for (int j = 0; j < 4; j++) {
            if (isW) {
                g_a[r0 + j] = acc[j];
                double a = (double)acc[j];
                da += a; da2 += a * a;
            } else {
                g_fsq[rb + j] = acc[j];
            }
        }
        sda[wid] = da; sda2[wid] = da2;
    }
    __syncthreads();
    if (tid == 0) {
        double da = 0.0, da2 = 0.0;
        #pragma unroll
        for (int j = 0; j < 8; j++) { da += sda[j]; da2 += sda2[j]; }
        g_ap[blockIdx.x] = da; g_a2p[blockIdx.x] = da2;
    }
}

// ---------------- su: per-block fp64 (sum s^2, sum u*s) ----------------
// 64 blocks x 256: warp per k (512 warps)
__global__ void __launch_bounds__(256) k_su() {
    __shared__ double ss2[8], sus[8];
    int tid = threadIdx.x, wid = tid >> 5, lane = tid & 31;
    int k = (int)blockIdx.x * 8 + wid;
    const float4* row = reinterpret_cast<const float4*>(g_Wt + (size_t)k * 4096);
    const float4* av  = reinterpret_cast<const float4*>(g_a);
    float s = 0.f, u = 0.f;
    #pragma unroll 8
    for (int q = 0; q < 32; q++) {
        int i4 = lane + q * 32;
        if (i4 < 1000) {
            float4 w = row[i4];
            float4 a = av[i4];
            s += w.x + w.y + w.z + w.w;
            u += a.x*w.x + a.y*w.y + a.z*w.z + a.w*w.w;
        }
    }
    #pragma unroll
    for (int o = 16; o > 0; o >>= 1) {
        s += __shfl_down_sync(0xffffffffu, s, o);
        u += __shfl_down_sync(0xffffffffu, u, o);
    }
    if (lane == 0) {
        ss2[wid] = (double)s * (double)s;
        sus[wid] = (double)u * (double)s;
    }
    __syncthreads();
    if (tid == 0) {
        double s2 = 0.0, us = 0.0;
        #pragma unroll
        for (int j = 0; j < 8; j++) { s2 += ss2[j]; us += sus[j]; }
        g_s2p[blockIdx.x] = s2; g_usp[blockIdx.x] = us;
    }
}

// ---------------- pipeline layout ----------------
#define STG       4
#define STG_BYTES 16384
#define OFF_A     1024
#define OFF_B     (1024 + STG*STG_BYTES)
#define SMEM_TC   (1024 + 2*STG*STG_BYTES)
#define IDESC_TF32 ((1u<<4) | (2u<<7) | (2u<<10) | (16u<<17) | (8u<<24))
#define GK_NCHUNK 25
#define KC      32
#define NCHUNK  16

#if HAS_TC
__device__ __forceinline__ void gram_load_chunk(uint32_t sb, int stage, int c,
                                                int K0, int L0, int mbase, int tid) {
    int moff = mbase + c * 32;
    uint32_t dA = sb + OFF_A + stage * STG_BYTES;
    uint32_t dB = sb + OFF_B + stage * STG_BYTES;
    #pragma unroll
    for (int p = 0; p < 8; p++) {
        int idx = p * 128 + tid;
        int r = idx >> 3, seg = idx & 7;
        uint32_t off = swz((uint32_t)(r * 128 + seg * 16));
        cp16(dA + off, g_Wt + (size_t)(K0 + r) * 4096 + moff + seg * 4, true);
        cp16(dB + off, g_Wt + (size_t)(L0 + r) * 4096 + moff + seg * 4, true);
    }
}
#endif

__global__ void __launch_bounds__(128, 1) k_gram_tc() {
#if HAS_TC
    extern __shared__ char smem[];
    uint32_t sb = smem_u32(smem);
    int tid = threadIdx.x, wid = tid >> 5, lane = tid & 31;
    int t = blockIdx.x / 5, z = blockIdx.x % 5;
    int K0 = c_ti[t] * 128, L0 = c_tj[t] * 128, mbase = z * 800;

    if (tid < 4) MBAR_INIT(sb + tid * 8, 1);
    if (wid == 0) { TC_ALLOC(sb + 32, 128); TC_RELINQ(); }
    __syncthreads();
    uint32_t tmem;
    asm volatile("ld.shared.b32 %0, [%1];" : "=r"(tmem) : "r"(sb + 32));

    #pragma unroll
    for (int c0 = 0; c0 < 3; c0++) {
        gram_load_chunk(sb, c0, c0, K0, L0, mbase, tid);
        asm volatile("cp.async.commit_group;" ::: "memory");
    }
    uint32_t phv = 0;
    for (int c = 0; c < GK_NCHUNK; c++) {
        int s = c & 3;
        if (c + 3 < GK_NCHUNK) {
            int so = (c + 3) & 3;
            if (c >= 1) {
                MBAR_WAIT(sb + so * 8, (phv >> so) & 1u);
                phv ^= (1u << so);
            }
            gram_load_chunk(sb, so, c + 3, K0, L0, mbase, tid);
        }
        asm volatile("cp.async.commit_group;" ::: "memory");
        asm volatile("cp.async.wait_group 3;" ::: "memory");
        __syncthreads();
        if (wid == 0 && elect_one()) {
            asm volatile("fence.proxy.async.shared::cta;" ::: "memory");
            uint64_t ad = make_desc(sb + OFF_A + s * STG_BYTES);
            uint64_t bd = make_desc(sb + OFF_B + s * STG_BYTES);
            #pragma unroll
            for (int k = 0; k < 4; k++)
                mma_tf32(tmem, ad + k * 2, bd + k * 2, IDESC_TF32,
                         (c > 0 || k > 0) ? 1u : 0u);
            TC_COMMIT(sb + s * 8);
        }
    }
    __syncthreads();
    {
        int so = (GK_NCHUNK - 1) & 3;
        MBAR_WAIT(sb + so * 8, (phv >> so) & 1u);
    }
    TC_FENCE_AFTER();

    float* dst = g_G2 + ((size_t)blockIdx.x << 14);
    int row = wid * 32 + lane;
    #pragma unroll
    for (int j0 = 0; j0 < 128; j0 += 32) {
        uint32_t r[32];
        LDTM_X32(r, tmem + j0);
        TC_WAIT_LD();
        #pragma unroll
        for (int j4 = 0; j4 < 8; j4++) {
            float4 v = make_float4(__uint_as_float(r[j4*4+0]), __uint_as_float(r[j4*4+1]),
                                   __uint_as_float(r[j4*4+2]), __uint_as_float(r[j4*4+3]));
            *reinterpret_cast<float4*>(&dst[(size_t)row * 128 + j0 + j4 * 4]) = v;
        }
    }
    TC_FENCE_BEFORE();
    __syncthreads();
    if (wid == 0) TC_DEALLOC(tmem, 128);
#else
    int t = blockIdx.x / 5, z = blockIdx.x % 5;
    int K0 = c_ti[t] * 128, L0 = c_tj[t] * 128, mbase = z * 800;
    float* dst = g_G2 + ((size_t)blockIdx.x << 14);
    for (int e = threadIdx.x; e < 16384; e += blockDim.x) {
        int k = K0 + (e >> 7), l = L0 + (e & 127);
        float acc = 0.f;
        for (int m = 0; m < 800; m++)
            acc = fmaf(g_Wt[(size_t)k * 4096 + mbase + m],
                       g_Wt[(size_t)l * 4096 + mbase + m], acc);
        dst[e] = acc;
    }
#endif
}

#if HAS_TC
__device__ __forceinline__ void fw_load_chunk(uint32_t sb, int stage, int c,
                                              const float* __restrict__ W,
                                              const float* __restrict__ F,
                                              int m0, int b0, int tid) {
    int kc = c * KC;
    uint32_t dA = sb + OFF_A + stage * STG_BYTES;
    uint32_t dB = sb + OFF_B + stage * STG_BYTES;
    #pragma unroll
    for (int p = 0; p < 8; p++) {
        int idx = p * 128 + tid;
        int r = idx >> 3, seg = idx & 7;
        uint32_t off = swz((uint32_t)(r * 128 + seg * 16));
        int m = m0 + r;
        bool v = (m < MC);
        cp16(dA + off, W + (size_t)(v ? m : 0) * HID + kc + seg * 4, v);
        cp16(dB + off, F + (size_t)(b0 + r) * HID + kc + seg * 4, true);
    }
}
#endif

__global__ void __launch_bounds__(128, 1) k_fw_tc(const float* __restrict__ F,
                                                  const float* __restrict__ W,
                                                  float* __restrict__ out) {
#if HAS_TC
    extern __shared__ char smem[];
    uint32_t sb = smem_u32(smem);
    int tid = threadIdx.x, wid = tid >> 5, lane = tid & 31;
    int m0 = (int)blockIdx.x * 128, b0 = (int)blockIdx.y * 128;

    if (tid < 4) MBAR_INIT(sb + tid * 8, 1);
    if (wid == 0) { TC_ALLOC(sb + 32, 128); TC_RELINQ(); }
    __syncthreads();
    uint32_t tmem;
    asm volatile("ld.shared.b32 %0, [%1];" : "=r"(tmem) : "r"(sb + 32));

    #pragma unroll
    for (int c0 = 0; c0 < 3; c0++) {
        fw_load_chunk(sb, c0, c0, W, F, m0, b0, tid);
        asm volatile("cp.async.commit_group;" ::: "memory");
    }
    uint32_t phv = 0;
    for (int c = 0; c < NCHUNK; c++) {
        int s = c & 3;
        if (c + 3 < NCHUNK) {
            int so = (c + 3) & 3;
            if (c >= 1) {
                MBAR_WAIT(sb + so * 8, (phv >> so) & 1u);
                phv ^= (1u << so);
            }
            fw_load_chunk(sb, so, c + 3, W, F, m0, b0, tid);
        }
        asm volatile("cp.async.commit_group;" ::: "memory");
        asm volatile("cp.async.wait_group 3;" ::: "memory");
        __syncthreads();
        if (wid == 0 && elect_one()) {
            asm volatile("fence.proxy.async.shared::cta;" ::: "memory");
            uint64_t ad = make_desc(sb + OFF_A + s * STG_BYTES);
            uint64_t bd = make_desc(sb + OFF_B + s * STG_BYTES);
            #pragma unroll
            for (int k = 0; k < 4; k++)
                mma_tf32(tmem, ad + k * 2, bd + k * 2, IDESC_TF32,
                         (c > 0 || k > 0) ? 1u : 0u);
            TC_COMMIT(sb + s * 8);
        }
    }
    __syncthreads();
    MBAR_WAIT(sb + 3 * 8, (phv >> 3) & 1u);
    TC_FENCE_AFTER();

    int m = m0 + wid * 32 + lane;
    float a = (m < MC) ? __ldg(&g_a[m]) : __int_as_float(0x7f800000);
    int grp = m >> 2;
    #pragma unroll
    for (int j0 = 0; j0 < 128; j0 += 32) {
        uint32_t r[32];
        LDTM_X32(r, tmem + j0);
        TC_WAIT_LD();
        #pragma unroll
        for (int jj = 0; jj < 32; jj++) {
            float fw = __uint_as_float(r[jj]);
            float x = fmaf(-2.f, fw, a);
            x = fminf(x, __shfl_xor_sync(0xffffffffu, x, 1));
            x = fminf(x, __shfl_xor_sync(0xffffffffu, x, 2));
            if ((lane & 3) == 0 && m < MC) {
                int b = b0 + j0 + jj;
                out[(size_t)b * (NCLS + 1) + grp] =
                    expf(-(__ldg(&g_fsq[b]) + x) * INV_SIGMA);
            }
        }
    }
    TC_FENCE_BEFORE();
    __syncthreads();
    if (wid == 0) TC_DEALLOC(tmem, 128);
#else
    int tid = threadIdx.x;
    int m0 = (int)blockIdx.x * 128, b0 = (int)blockIdx.y * 128;
    int m = m0 + tid;
    if (m >= MC) return;
    float a = g_a[m];
    int grp = m >> 2;
    const float* wrow = W + (size_t)m * HID;
    for (int jb = 0; jb < 128; jb++) {
        int b = b0 + jb;
        const float* frow = F + (size_t)b * HID;
        float dot = 0.f;
        for (int k = 0; k < HID; k++) dot = fmaf(wrow[k], frow[k], dot);
        float x = fmaf(-2.f, dot, a);
        x = fminf(x, __shfl_xor_sync(0xffffffffu, x, 1));
        x = fminf(x, __shfl_xor_sync(0xffffffffu, x, 2));
        if ((tid & 3) == 0)
            out[(size_t)b * (NCLS + 1) + grp] =
                expf(-(g_fsq[b] + x) * INV_SIGMA);
    }
#endif
}

// ---------------- f2 + fused finalize (last-arriving block) ----------------
// 160 blocks x 256. Deterministic: the finalize sums fixed partial arrays.
__global__ void __launch_bounds__(256) k_f2fin(float* __restrict__ out) {
    __shared__ double sd[8], sd2[8], sd3[8], sd4[8], sd5[8];
    __shared__ bool is_last;
    __shared__ float rw_s;
    int tid = threadIdx.x, wid = tid >> 5, lane = tid & 31;

    // f2 partial
    double acc = 0.0;
    for (int i = (int)blockIdx.x * 256 + tid; i < 10 * 16384; i += 160 * 256) {
        int t = i >> 14, e = i & 16383;
        float g = 0.f;
        #pragma unroll
        for (int z = 0; z < 5; z++) g += g_G2[((size_t)(t * 5 + z) << 14) + e];
        double w = (c_ti[t] == c_tj[t]) ? 1.0 : 2.0;
        acc += w * (double)g * (double)g;
    }
    #pragma unroll
    for (int o = 16; o > 0; o >>= 1)
        acc += __shfl_down_sync(0xffffffffu, acc, o);
    if (lane == 0) sd[wid] = acc;
    __syncthreads();
    if (tid == 0) {
        double f = 0.0;
        #pragma unroll
        for (int j = 0; j < 8; j++) f += sd[j];
        g_f2p[blockIdx.x] = f;
    }
    // arrival
    __threadfence();
    __syncthreads();
    if (tid == 0) {
        unsigned v = atomicAdd(&g_ctr, 1u);
        is_last = (v == 159u);
    }
    __syncthreads();
    if (!is_last) return;
    if (tid == 0) g_ctr = 0;      // reset for next graph replay
    __threadfence();

    // final reduction over partial arrays (<=160 elements each)
    double la  = (tid < 141) ? g_ap[tid]  : 0.0;
    double la2 = (tid < 141) ? g_a2p[tid] : 0.0;
    double ls2 = (tid < 64)  ? g_s2p[tid] : 0.0;
    double lus = (tid < 64)  ? g_usp[tid] : 0.0;
    double lf2 = (tid < 160) ? g_f2p[tid] : 0.0;
    #pragma unroll
    for (int o = 16; o > 0; o >>= 1) {
        la  += __shfl_down_sync(0xffffffffu, la,  o);
        la2 += __shfl_down_sync(0xffffffffu, la2, o);
        ls2 += __shfl_down_sync(0xffffffffu, ls2, o);
        lus += __shfl_down_sync(0xffffffffu, lus, o);
        lf2 += __shfl_down_sync(0xffffffffu, lf2, o);
    }
    if (lane == 0) { sd[wid]=la; sd2[wid]=la2; sd3[wid]=ls2; sd4[wid]=lus; sd5[wid]=lf2; }
    __syncthreads();
    if (tid == 0) {
        double sum_a=0, sum_a2=0, s2=0, sum_at=0, F2=0;
        #pragma unroll
        for (int j = 0; j < 8; j++) {
            sum_a += sd[j]; sum_a2 += sd2[j]; s2 += sd3[j];
            sum_at += sd4[j]; F2 += sd5[j];
        }
        double mc = (double)MC;
        double denom = 2.0 / (mc * mc - mc);
        double S1 = mc * sum_a - s2;
        double mu = denom * S1;
        double S2 = mc * sum_a2 + sum_a * sum_a + 2.0 * F2 - 4.0 * sum_at;
        rw_s = (float)(denom * S2 - mu * mu);
    }
    __syncthreads();
    #pragma unroll
    for (int j = 0; j < 2; j++)
        out[(size_t)(tid * 2 + j) * (NCLS + 1) + NCLS] = rw_s;
}

extern "C" void kernel_launch(void* const* d_in, const int* in_sizes, int n_in,
                              void* d_out, int out_size) {
    const float* F = (const float*)d_in[0];   // [512,512]
    const float* W = (const float*)d_in[1];   // [4000,512]
    float* out = (float*)d_out;               // [512,1001]
    (void)in_sizes; (void)n_in; (void)out_size;

    static bool inited = false;
    static cudaStream_t s1;
    static cudaEvent_t evA, evT, evB;
    if (!inited) {
        cudaFuncSetAttribute(k_fw_tc, cudaFuncAttributeMaxDynamicSharedMemorySize,
                             SMEM_TC);
        cudaFuncSetAttribute(k_gram_tc, cudaFuncAttributeMaxDynamicSharedMemorySize,
                             SMEM_TC);
        cudaStreamCreateWithFlags(&s1, cudaStreamNonBlocking);
        cudaEventCreateWithFlags(&evA, cudaEventDisableTiming);
        cudaEventCreateWithFlags(&evT, cudaEventDisableTiming);
        cudaEventCreateWithFlags(&evB, cudaEventDisableTiming);
        inited = true;
    }

    // fork
    cudaEventRecord(evA, 0);
    cudaStreamWaitEvent(s1, evA, 0);

    // chain 0: transpose -> gram
    k_transpose<<<2000, 256>>>(W);
    cudaEventRecord(evT, 0);                  // Wt ready
    k_gram_tc<<<50, 128, SMEM_TC>>>();

    // chain 1: pre -> (wait Wt) su -> fw
    k_pre<<<141, 256, 0, s1>>>(W, F);
    cudaStreamWaitEvent(s1, evT, 0);
    k_su<<<64, 256, 0, s1>>>();
    k_fw_tc<<<dim3(32, 4), 128, SMEM_TC, s1>>>(F, W, out);
    cudaEventRecord(evB, s1);

    // join: f2 + fused finalize (needs gram [program order] and chain1 [evB])
    cudaStreamWaitEvent(0, evB, 0);
    k_f2fin<<<160, 256>>>(out);
}

// round 12
// speedup vs baseline: 1.4187x; 1.0438x over previous
#include <cuda_runtime.h>
#include <math.h>
#include <stdint.h>

#define BATCH 512
#define HID   512
#define NCLS  1000
#define MC    4000
#define INV_SIGMA (1.0f/10.0f)

#if defined(__CUDA_ARCH__) && (__CUDA_ARCH__ == 1030) && defined(__CUDA_ARCH_FEAT_SM103_ALL)
#define HAS_TC 1
#else
#define HAS_TC 0
#endif

// ---------------- scratch ----------------
__device__ __align__(16) float g_a[4096];        // ||w_m||^2 (exact fp32)
__device__ __align__(16) float g_fsq[BATCH];     // ||f_b||^2
__device__ __align__(16) float g_Wt[512*4096];   // W^T, tf32-RN-rounded, stride 4096
__device__ __align__(16) float g_G2[10*5*16384]; // Gram partials
__device__ double g_ap[141], g_a2p[141];         // per-block sum a, sum a^2
__device__ double g_s2p[128], g_usp[128];        // per-block sum s^2, sum u*s
__device__ double g_f2p[160];                    // per-block F2 partials
__device__ unsigned g_ctr = 0;                   // arrival counter (reset each run)

__constant__ int c_ti[10] = {0,0,0,0,1,1,1,2,2,3};
__constant__ int c_tj[10] = {0,1,2,3,1,2,3,2,3,3};

// ---------------- PTX helpers ----------------
__device__ __forceinline__ uint32_t smem_u32(const void* p) {
    uint32_t a;
    asm("{ .reg .u64 t; cvta.to.shared.u64 t, %1; cvt.u32.u64 %0, t; }"
        : "=r"(a) : "l"(p));
    return a;
}
__device__ __forceinline__ uint32_t elect_one() {
    uint32_t pred;
    asm volatile("{\n\t.reg .pred p;\n\telect.sync _|p, 0xFFFFFFFF;\n\t"
                 "selp.b32 %0, 1, 0, p;\n\t}" : "=r"(pred));
    return pred;
}
__device__ __forceinline__ float tf32_rn(float x) {
    float r;
    asm("cvt.rna.tf32.f32 %0, %1;" : "=f"(r) : "f"(x));
    return r;
}
#define MBAR_INIT(addr, cnt) \
    asm volatile("mbarrier.init.shared.b64 [%0], %1;" :: "r"(addr), "r"(cnt) : "memory")
#define MBAR_WAIT(addr, par) do { \
    uint32_t _m = (addr), _p = (par), _d; \
    asm volatile("{\n\t.reg .pred p;\n\t" \
        "mbarrier.try_wait.parity.acquire.cta.shared::cta.b64 p, [%1], %2;\n\t" \
        "selp.b32 %0, 1, 0, p;\n\t}" : "=r"(_d) : "r"(_m), "r"(_p) : "memory"); \
    if (!_d) { \
        asm volatile("{\n\t.reg .pred P1;\n\tWL%=:\n\t" \
            "mbarrier.try_wait.parity.acquire.cta.shared::cta.b64 P1, [%0], %1, 0x989680;\n\t" \
            "@P1 bra.uni WD%=;\n\tbra.uni WL%=;\n\tWD%=:\n\t}" \
            :: "r"(_m), "r"(_p) : "memory"); \
    } } while (0)

#if HAS_TC
#define TC_ALLOC(smem_addr, n) \
    asm volatile("tcgen05.alloc.cta_group::1.sync.aligned.shared::cta.b32 [%0], %1;" \
        :: "r"(smem_addr), "r"(n) : "memory")
#define TC_DEALLOC(tmem, n) \
    asm volatile("tcgen05.dealloc.cta_group::1.sync.aligned.b32 %0, %1;" :: "r"(tmem), "r"(n))
#define TC_RELINQ() \
    asm volatile("tcgen05.relinquish_alloc_permit.cta_group::1.sync.aligned;")
#define TC_COMMIT(mbar) \
    asm volatile("tcgen05.commit.cta_group::1.mbarrier::arrive::one.shared::cluster.b64 [%0];" \
        :: "r"(mbar) : "memory")
#define TC_FENCE_AFTER() asm volatile("tcgen05.fence::after_thread_sync;" ::: "memory")
#define TC_FENCE_BEFORE() asm volatile("tcgen05.fence::before_thread_sync;" ::: "memory")
#define TC_WAIT_LD() asm volatile("tcgen05.wait::ld.sync.aligned;" ::: "memory")
#define LDTM_X32(r, addr) \
    asm volatile("tcgen05.ld.sync.aligned.32x32b.x32.b32 " \
        "{%0,%1,%2,%3,%4,%5,%6,%7,%8,%9,%10,%11,%12,%13,%14,%15," \
        "%16,%17,%18,%19,%20,%21,%22,%23,%24,%25,%26,%27,%28,%29,%30,%31}, [%32];" \
        : "=r"((r)[0]),"=r"((r)[1]),"=r"((r)[2]),"=r"((r)[3]), \
          "=r"((r)[4]),"=r"((r)[5]),"=r"((r)[6]),"=r"((r)[7]), \
          "=r"((r)[8]),"=r"((r)[9]),"=r"((r)[10]),"=r"((r)[11]), \
          "=r"((r)[12]),"=r"((r)[13]),"=r"((r)[14]),"=r"((r)[15]), \
          "=r"((r)[16]),"=r"((r)[17]),"=r"((r)[18]),"=r"((r)[19]), \
          "=r"((r)[20]),"=r"((r)[21]),"=r"((r)[22]),"=r"((r)[23]), \
          "=r"((r)[24]),"=r"((r)[25]),"=r"((r)[26]),"=r"((r)[27]), \
          "=r"((r)[28]),"=r"((r)[29]),"=r"((r)[30]),"=r"((r)[31]) \
        : "r"(addr))

static __device__ __forceinline__ uint64_t make_desc(uint32_t addr) {
    const uint64_t base = (uint64_t(2) << 61) | (uint64_t(1) << 46)
                        | (uint64_t(64) << 32) | (uint64_t(1) << 16);
    return base | ((uint64_t)(addr >> 4) & 0x3FFF);
}
__device__ __forceinline__ void mma_tf32(uint32_t d, uint64_t ad, uint64_t bd,
                                         uint32_t idesc, uint32_t en) {
    asm volatile("{\n\t.reg .pred p;\n\tsetp.ne.u32 p, %5, 0;\n\t"
        "tcgen05.mma.cta_group::1.kind::tf32 [%0], %1, %2, %3, {%4,%4,%4,%4}, p;\n\t}"
        :: "r"(d), "l"(ad), "l"(bd), "r"(idesc), "r"(0u), "r"(en) : "memory");
}
#endif  // HAS_TC

__device__ __forceinline__ uint32_t swz(uint32_t o) { return o ^ ((o >> 3) & 0x70); }

__device__ __forceinline__ void cp16(uint32_t dst, const void* src, bool valid) {
    int sz = valid ? 16 : 0;
    asm volatile("cp.async.cg.shared.global [%0], [%1], 16, %2;"
                 :: "r"(dst), "l"(src), "r"(sz));
}

// ---------------- transpose + tf32-RN round ----------------
__global__ void __launch_bounds__(256) k_transpose(const float* __restrict__ W) {
    __shared__ float tile[32][33];
    int k0 = (blockIdx.x & 15) * 32, m0 = (blockIdx.x >> 4) * 32;
    int x = threadIdx.x & 31, y = threadIdx.x >> 5;
    #pragma unroll
    for (int i = 0; i < 4; i++)
        tile[y + i * 8][x] = W[(size_t)(m0 + y + i * 8) * HID + k0 + x];
    __syncthreads();
    #pragma unroll
    for (int i = 0; i < 4; i++)
        g_Wt[(size_t)(k0 + y + i * 8) * 4096 + m0 + x] = tf32_rn(tile[x][y + i * 8]);
}

// ---------------- pre: a_m, fsq + per-block fp64 (sum a, sum a^2) ----------------
__global__ void __launch_bounds__(256) k_pre(const float* __restrict__ W,
                                             const float* __restrict__ F) {
    __shared__ double sda[8], sda2[8];
    int tid = threadIdx.x, wid = tid >> 5, lane = tid & 31;
    int warp = (int)blockIdx.x * 8 + wid;
    int r0 = warp * 4;
    bool isW = (r0 < MC);
    const float* base = isW ? W : F;
    int rb = isW ? r0 : (r0 - MC);
    float4 v[4][4];
    #pragma unroll
    for (int j = 0; j < 4; j++)
        #pragma unroll
        for (int q = 0; q < 4; q++)
            v[j][q] = reinterpret_cast<const float4*>(
                base + (size_t)(rb + j) * HID)[lane + q * 32];
    float acc[4];
    #pragma unroll
    for (int j = 0; j < 4; j++) {
        float a = 0.f;
        #pragma unroll
        for (int q = 0; q < 4; q++)
            a += v[j][q].x*v[j][q].x + v[j][q].y*v[j][q].y
               + v[j][q].z*v[j][q].z + v[j][q].w*v[j][q].w;
        acc[j] = a;
    }
    #pragma unroll
    for (int o = 16; o > 0; o >>= 1)
        #pragma unroll
        for (int j = 0; j < 4; j++)
            acc[j] += __shfl_down_sync(0xffffffffu, acc[j], o);
    if (lane == 0) {
        double da = 0.0, da2 = 0.0;
        #pragma unroll
        for (int j = 0; j < 4; j++) {
            if (isW) {
                g_a[r0 + j] = acc[j];
                double a = (double)acc[j];
                da += a; da2 += a * a;
            } else {
                g_fsq[rb + j] = acc[j];
            }
        }
        sda[wid] = da; sda2[wid] = da2;
    }
    __syncthreads();
    if (tid == 0) {
        double da = 0.0, da2 = 0.0;
        #pragma unroll
        for (int j = 0; j < 8; j++) { da += sda[j]; da2 += sda2[j]; }
        g_ap[blockIdx.x] = da; g_a2p[blockIdx.x] = da2;
    }
}

// ---------------- su: 128 blocks x 8 warps; 2 warps per k (half-rows) ----------
__global__ void __launch_bounds__(256) k_su() {
    __shared__ float sh_s[4][2], sh_u[4][2];
    __shared__ double sh_d[4][2];
    int tid = threadIdx.x, wid = tid >> 5, lane = tid & 31;
    int kl = wid >> 1, half = wid & 1;               // 4 local k, 2 halves
    int k = (int)blockIdx.x * 4 + kl;
    const float4* row = reinterpret_cast<const float4*>(g_Wt + (size_t)k * 4096)
                      + half * 500;
    const float4* av  = reinterpret_cast<const float4*>(g_a) + half * 500;
    float s = 0.f, u = 0.f;
    #pragma unroll
    for (int q = 0; q < 16; q++) {
        int idx = lane + q * 32;
        if (idx < 500) {
            float4 w = row[idx];
            float4 a = av[idx];
            s += w.x + w.y + w.z + w.w;
            u += a.x*w.x + a.y*w.y + a.z*w.z + a.w*w.w;
        }
    }
    #pragma unroll
    for (int o = 16; o > 0; o >>= 1) {
        s += __shfl_down_sync(0xffffffffu, s, o);
        u += __shfl_down_sync(0xffffffffu, u, o);
    }
    if (lane == 0) { sh_s[kl][half] = s; sh_u[kl][half] = u; }
    __syncthreads();
    if (tid < 4) {
        float sk = sh_s[tid][0] + sh_s[tid][1];
        float uk = sh_u[tid][0] + sh_u[tid][1];
        sh_d[tid][0] = (double)sk * (double)sk;
        sh_d[tid][1] = (double)uk * (double)sk;
    }
    __syncthreads();
    if (tid == 0) {
        double s2 = 0.0, us = 0.0;
        #pragma unroll
        for (int j = 0; j < 4; j++) { s2 += sh_d[j][0]; us += sh_d[j][1]; }
        g_s2p[blockIdx.x] = s2; g_usp[blockIdx.x] = us;
    }
}

// ---------------- pipeline layout ----------------
#define STG       4
#define STG_BYTES 16384
#define OFF_A     1024
#define OFF_B     (1024 + STG*STG_BYTES)
#define SMEM_TC   (1024 + 2*STG*STG_BYTES)
#define IDESC_TF32 ((1u<<4) | (2u<<7) | (2u<<10) | (16u<<17) | (8u<<24))
#define GK_NCHUNK 25
#define KC      32
#define NCHUNK  16

#if HAS_TC
__device__ __forceinline__ void gram_load_chunk(uint32_t sb, int stage, int c,
                                                int K0, int L0, int mbase, int tid) {
    int moff = mbase + c * 32;
    uint32_t dA = sb + OFF_A + stage * STG_BYTES;
    uint32_t dB = sb + OFF_B + stage * STG_BYTES;
    #pragma unroll
    for (int p = 0; p < 8; p++) {
        int idx = p * 128 + tid;
        int r = idx >> 3, seg = idx & 7;
        uint32_t off = swz((uint32_t)(r * 128 + seg * 16));
        cp16(dA + off, g_Wt + (size_t)(K0 + r) * 4096 + moff + seg * 4, true);
        cp16(dB + off, g_Wt + (size_t)(L0 + r) * 4096 + moff + seg * 4, true);
    }
}
#endif

__global__ void __launch_bounds__(128, 1) k_gram_tc() {
#if HAS_TC
    extern __shared__ char smem[];
    uint32_t sb = smem_u32(smem);
    int tid = threadIdx.x, wid = tid >> 5, lane = tid & 31;
    int t = blockIdx.x / 5, z = blockIdx.x % 5;
    int K0 = c_ti[t] * 128, L0 = c_tj[t] * 128, mbase = z * 800;

    if (tid < 4) MBAR_INIT(sb + tid * 8, 1);
    if (wid == 0) { TC_ALLOC(sb + 32, 128); TC_RELINQ(); }
    __syncthreads();
    uint32_t tmem;
    asm volatile("ld.shared.b32 %0, [%1];" : "=r"(tmem) : "r"(sb + 32));

    #pragma unroll
    for (int c0 = 0; c0 < 3; c0++) {
        gram_load_chunk(sb, c0, c0, K0, L0, mbase, tid);
        asm volatile("cp.async.commit_group;" ::: "memory");
    }
    uint32_t phv = 0;
    for (int c = 0; c < GK_NCHUNK; c++) {
        int s = c & 3;
        if (c + 3 < GK_NCHUNK) {
            int so = (c + 3) & 3;
            if (c >= 1) {
                MBAR_WAIT(sb + so * 8, (phv >> so) & 1u);
                phv ^= (1u << so);
            }
            gram_load_chunk(sb, so, c + 3, K0, L0, mbase, tid);
        }
        asm volatile("cp.async.commit_group;" ::: "memory");
        asm volatile("cp.async.wait_group 3;" ::: "memory");
        __syncthreads();
        if (wid == 0 && elect_one()) {
            asm volatile("fence.proxy.async.shared::cta;" ::: "memory");
            uint64_t ad = make_desc(sb + OFF_A + s * STG_BYTES);
            uint64_t bd = make_desc(sb + OFF_B + s * STG_BYTES);
            #pragma unroll
            for (int k = 0; k < 4; k++)
                mma_tf32(tmem, ad + k * 2, bd + k * 2, IDESC_TF32,
                         (c > 0 || k > 0) ? 1u : 0u);
            TC_COMMIT(sb + s * 8);
        }
    }
    __syncthreads();
    {
        int so = (GK_NCHUNK - 1) & 3;
        MBAR_WAIT(sb + so * 8, (phv >> so) & 1u);
    }
    TC_FENCE_AFTER();

    float* dst = g_G2 + ((size_t)blockIdx.x << 14);
    int row = wid * 32 + lane;
    #pragma unroll
    for (int j0 = 0; j0 < 128; j0 += 32) {
        uint32_t r[32];
        LDTM_X32(r, tmem + j0);
        TC_WAIT_LD();
        #pragma unroll
        for (int j4 = 0; j4 < 8; j4++) {
            float4 v = make_float4(__uint_as_float(r[j4*4+0]), __uint_as_float(r[j4*4+1]),
                                   __uint_as_float(r[j4*4+2]), __uint_as_float(r[j4*4+3]));
            *reinterpret_cast<float4*>(&dst[(size_t)row * 128 + j0 + j4 * 4]) = v;
        }
    }
    TC_FENCE_BEFORE();
    __syncthreads();
    if (wid == 0) TC_DEALLOC(tmem, 128);
#else
    int t = blockIdx.x / 5, z = blockIdx.x % 5;
    int K0 = c_ti[t] * 128, L0 = c_tj[t] * 128, mbase = z * 800;
    float* dst = g_G2 + ((size_t)blockIdx.x << 14);
    for (int e = threadIdx.x; e < 16384; e += blockDim.x) {
        int k = K0 + (e >> 7), l = L0 + (e & 127);
        float acc = 0.f;
        for (int m = 0; m < 800; m++)
            acc = fmaf(g_Wt[(size_t)k * 4096 + mbase + m],
                       g_Wt[(size_t)l * 4096 + mbase + m], acc);
        dst[e] = acc;
    }
#endif
}

#if HAS_TC
__device__ __forceinline__ void fw_load_chunk(uint32_t sb, int stage, int c,
                                              const float* __restrict__ W,
                                              const float* __restrict__ F,
                                              int m0, int b0, int tid) {
    int kc = c * KC;
    uint32_t dA = sb + OFF_A + stage * STG_BYTES;
    uint32_t dB = sb + OFF_B + stage * STG_BYTES;
    #pragma unroll
    for (int p = 0; p < 8; p++) {
        int idx = p * 128 + tid;
        int r = idx >> 3, seg = idx & 7;
        uint32_t off = swz((uint32_t)(r * 128 + seg * 16));
        int m = m0 + r;
        bool v = (m < MC);
        cp16(dA + off, W + (size_t)(v ? m : 0) * HID + kc + seg * 4, v);
        cp16(dB + off, F + (size_t)(b0 + r) * HID + kc + seg * 4, true);
    }
}
#endif

__global__ void __launch_bounds__(128, 1) k_fw_tc(const float* __restrict__ F,
                                                  const float* __restrict__ W,
                                                  float* __restrict__ out) {
#if HAS_TC
    extern __shared__ char smem[];
    uint32_t sb = smem_u32(smem);
    int tid = threadIdx.x, wid = tid >> 5, lane = tid & 31;
    int m0 = (int)blockIdx.x * 128, b0 = (int)blockIdx.y * 128;

    if (tid < 4) MBAR_INIT(sb + tid * 8, 1);
    if (wid == 0) { TC_ALLOC(sb + 32, 128); TC_RELINQ(); }
    __syncthreads();
    uint32_t tmem;
    asm volatile("ld.shared.b32 %0, [%1];" : "=r"(tmem) : "r"(sb + 32));

    #pragma unroll
    for (int c0 = 0; c0 < 3; c0++) {
        fw_load_chunk(sb, c0, c0, W, F, m0, b0, tid);
        asm volatile("cp.async.commit_group;" ::: "memory");
    }
    uint32_t phv = 0;
    for (int c = 0; c < NCHUNK; c++) {
        int s = c & 3;
        if (c + 3 < NCHUNK) {
            int so = (c + 3) & 3;
            if (c >= 1) {
                MBAR_WAIT(sb + so * 8, (phv >> so) & 1u);
                phv ^= (1u << so);
            }
            fw_load_chunk(sb, so, c + 3, W, F, m0, b0, tid);
        }
        asm volatile("cp.async.commit_group;" ::: "memory");
        asm volatile("cp.async.wait_group 3;" ::: "memory");
        __syncthreads();
        if (wid == 0 && elect_one()) {
            asm volatile("fence.proxy.async.shared::cta;" ::: "memory");
            uint64_t ad = make_desc(sb + OFF_A + s * STG_BYTES);
            uint64_t bd = make_desc(sb + OFF_B + s * STG_BYTES);
            #pragma unroll
            for (int k = 0; k < 4; k++)
                mma_tf32(tmem, ad + k * 2, bd + k * 2, IDESC_TF32,
                         (c > 0 || k > 0) ? 1u : 0u);
            TC_COMMIT(sb + s * 8);
        }
    }
    __syncthreads();
    MBAR_WAIT(sb + 3 * 8, (phv >> 3) & 1u);
    TC_FENCE_AFTER();

    int m = m0 + wid * 32 + lane;
    float a = (m < MC) ? __ldg(&g_a[m]) : __int_as_float(0x7f800000);
    int grp = m >> 2;
    #pragma unroll
    for (int j0 = 0; j0 < 128; j0 += 32) {
        uint32_t r[32];
        LDTM_X32(r, tmem + j0);
        TC_WAIT_LD();
        #pragma unroll
        for (int jj = 0; jj < 32; jj++) {
            float fw = __uint_as_float(r[jj]);
            float x = fmaf(-2.f, fw, a);
            x = fminf(x, __shfl_xor_sync(0xffffffffu, x, 1));
            x = fminf(x, __shfl_xor_sync(0xffffffffu, x, 2));
            if ((lane & 3) == 0 && m < MC) {
                int b = b0 + j0 + jj;
                out[(size_t)b * (NCLS + 1) + grp] =
                    expf(-(__ldg(&g_fsq[b]) + x) * INV_SIGMA);
            }
        }
    }
    TC_FENCE_BEFORE();
    __syncthreads();
    if (wid == 0) TC_DEALLOC(tmem, 128);
#else
    int tid = threadIdx.x;
    int m0 = (int)blockIdx.x * 128, b0 = (int)blockIdx.y * 128;
    int m = m0 + tid;
    if (m >= MC) return;
    float a = g_a[m];
    int grp = m >> 2;
    const float* wrow = W + (size_t)m * HID;
    for (int jb = 0; jb < 128; jb++) {
        int b = b0 + jb;
        const float* frow = F + (size_t)b * HID;
        float dot = 0.f;
        for (int k = 0; k < HID; k++) dot = fmaf(wrow[k], frow[k], dot);
        float x = fmaf(-2.f, dot, a);
        x = fminf(x, __shfl_xor_sync(0xffffffffu, x, 1));
        x = fminf(x, __shfl_xor_sync(0xffffffffu, x, 2));
        if ((tid & 3) == 0)
            out[(size_t)b * (NCLS + 1) + grp] =
                expf(-(g_fsq[b] + x) * INV_SIGMA);
    }
#endif
}

// ---------------- f2 + fused finalize (last-arriving block) ----------------
__global__ void __launch_bounds__(256) k_f2fin(float* __restrict__ out) {
    __shared__ double sd[8], sd2[8], sd3[8], sd4[8], sd5[8];
    __shared__ bool is_last;
    __shared__ float rw_s;
    int tid = threadIdx.x, wid = tid >> 5, lane = tid & 31;

    double acc = 0.0;
    for (int i = (int)blockIdx.x * 256 + tid; i < 10 * 16384; i += 160 * 256) {
        int t = i >> 14, e = i & 16383;
        float g = 0.f;
        #pragma unroll
        for (int z = 0; z < 5; z++) g += g_G2[((size_t)(t * 5 + z) << 14) + e];
        double w = (c_ti[t] == c_tj[t]) ? 1.0 : 2.0;
        acc += w * (double)g * (double)g;
    }
    #pragma unroll
    for (int o = 16; o > 0; o >>= 1)
        acc += __shfl_down_sync(0xffffffffu, acc, o);
    if (lane == 0) sd[wid] = acc;
    __syncthreads();
    if (tid == 0) {
        double f = 0.0;
        #pragma unroll
        for (int j = 0; j < 8; j++) f += sd[j];
        g_f2p[blockIdx.x] = f;
    }
    __threadfence();
    __syncthreads();
    if (tid == 0) {
        unsigned v = atomicAdd(&g_ctr, 1u);
        is_last = (v == 159u);
    }
    __syncthreads();
    if (!is_last) return;
    if (tid == 0) g_ctr = 0;
    __threadfence();

    double la  = (tid < 141) ? g_ap[tid]  : 0.0;
    double la2 = (tid < 141) ? g_a2p[tid] : 0.0;
    double ls2 = (tid < 128) ? g_s2p[tid] : 0.0;
    double lus = (tid < 128) ? g_usp[tid] : 0.0;
    double lf2 = (tid < 160) ? g_f2p[tid] : 0.0;
    #pragma unroll
    for (int o = 16; o > 0; o >>= 1) {
        la  += __shfl_down_sync(0xffffffffu, la,  o);
        la2 += __shfl_down_sync(0xffffffffu, la2, o);
        ls2 += __shfl_down_sync(0xffffffffu, ls2, o);
        lus += __shfl_down_sync(0xffffffffu, lus, o);
        lf2 += __shfl_down_sync(0xffffffffu, lf2, o);
    }
    if (lane == 0) { sd[wid]=la; sd2[wid]=la2; sd3[wid]=ls2; sd4[wid]=lus; sd5[wid]=lf2; }
    __syncthreads();
    if (tid == 0) {
        double sum_a=0, sum_a2=0, s2=0, sum_at=0, F2=0;
        #pragma unroll
        for (int j = 0; j < 8; j++) {
            sum_a += sd[j]; sum_a2 += sd2[j]; s2 += sd3[j];
            sum_at += sd4[j]; F2 += sd5[j];
        }
        double mc = (double)MC;
        double denom = 2.0 / (mc * mc - mc);
        double S1 = mc * sum_a - s2;
        double mu = denom * S1;
        double S2 = mc * sum_a2 + sum_a * sum_a + 2.0 * F2 - 4.0 * sum_at;
        rw_s = (float)(denom * S2 - mu * mu);
    }
    __syncthreads();
    #pragma unroll
    for (int j = 0; j < 2; j++)
        out[(size_t)(tid * 2 + j) * (NCLS + 1) + NCLS] = rw_s;
}

extern "C" void kernel_launch(void* const* d_in, const int* in_sizes, int n_in,
                              void* d_out, int out_size) {
    const float* F = (const float*)d_in[0];   // [512,512]
    const float* W = (const float*)d_in[1];   // [4000,512]
    float* out = (float*)d_out;               // [512,1001]
    (void)in_sizes; (void)n_in; (void)out_size;

    static bool inited = false;
    static cudaStream_t s1, s2;
    static cudaEvent_t evA, evT, evP, evS, evB;
    if (!inited) {
        cudaFuncSetAttribute(k_fw_tc, cudaFuncAttributeMaxDynamicSharedMemorySize,
                             SMEM_TC);
        cudaFuncSetAttribute(k_gram_tc, cudaFuncAttributeMaxDynamicSharedMemorySize,
                             SMEM_TC);
        cudaStreamCreateWithFlags(&s1, cudaStreamNonBlocking);
        cudaStreamCreateWithFlags(&s2, cudaStreamNonBlocking);
        cudaEventCreateWithFlags(&evA, cudaEventDisableTiming);
        cudaEventCreateWithFlags(&evT, cudaEventDisableTiming);
        cudaEventCreateWithFlags(&evP, cudaEventDisableTiming);
        cudaEventCreateWithFlags(&evS, cudaEventDisableTiming);
        cudaEventCreateWithFlags(&evB, cudaEventDisableTiming);
        inited = true;
    }

    // fork
    cudaEventRecord(evA, 0);
    cudaStreamWaitEvent(s1, evA, 0);

    // chain 0 (default): transpose -> gram
    k_transpose<<<2000, 256>>>(W);
    cudaEventRecord(evT, 0);                  // Wt ready
    k_gram_tc<<<50, 128, SMEM_TC>>>();

    // chain 1 (s1): pre -> fw   (fw no longer waits on Wt/su!)
    k_pre<<<141, 256, 0, s1>>>(W, F);
    cudaEventRecord(evP, s1);
    k_fw_tc<<<dim3(32, 4), 128, SMEM_TC, s1>>>(F, W, out);
    cudaEventRecord(evB, s1);

    // chain 2 (s2): su (needs Wt + a) — fully off the critical path
    cudaStreamWaitEvent(s2, evT, 0);
    cudaStreamWaitEvent(s2, evP, 0);
    k_su<<<128, 256, 0, s2>>>();
    cudaEventRecord(evS, s2);

    // join: f2 + fused finalize (gram by program order; fw + su via events)
    cudaStreamWaitEvent(0, evB, 0);
    cudaStreamWaitEvent(0, evS, 0);
    k_f2fin<<<160, 256>>>(out);
}

// round 13
// speedup vs baseline: 1.5651x; 1.1032x over previous
#include <cuda_runtime.h>
#include <math.h>
#include <stdint.h>

#define BATCH 512
#define HID   512
#define NCLS  1000
#define MC    4000
#define INV_SIGMA (1.0f/10.0f)

#if defined(__CUDA_ARCH__) && (__CUDA_ARCH__ == 1030) && defined(__CUDA_ARCH_FEAT_SM103_ALL)
#define HAS_TC 1
#else
#define HAS_TC 0
#endif

// ---------------- scratch ----------------
__device__ __align__(16) float g_a[4096];        // ||w_m||^2 (exact fp32)
__device__ __align__(16) float g_fsq[BATCH];     // ||f_b||^2
__device__ __align__(16) float g_Wt[512*4096];   // W^T, tf32-RN-rounded, stride 4096
__device__ __align__(16) float g_G2[100*16384];  // Gram partials: 10 tiles x 10 z
__device__ double g_ap[141], g_a2p[141];         // per-block sum a, sum a^2
__device__ double g_s2p[128], g_usp[128];        // per-block sum s^2, sum u*s
__device__ double g_f2p[160];                    // per-block F2 partials
__device__ unsigned g_ctr = 0;                   // arrival counter (reset each run)

__constant__ int c_ti[10] = {0,0,0,0,1,1,1,2,2,3};
__constant__ int c_tj[10] = {0,1,2,3,1,2,3,2,3,3};

// ---------------- PTX helpers ----------------
__device__ __forceinline__ uint32_t smem_u32(const void* p) {
    uint32_t a;
    asm("{ .reg .u64 t; cvta.to.shared.u64 t, %1; cvt.u32.u64 %0, t; }"
        : "=r"(a) : "l"(p));
    return a;
}
__device__ __forceinline__ uint32_t elect_one() {
    uint32_t pred;
    asm volatile("{\n\t.reg .pred p;\n\telect.sync _|p, 0xFFFFFFFF;\n\t"
                 "selp.b32 %0, 1, 0, p;\n\t}" : "=r"(pred));
    return pred;
}
__device__ __forceinline__ float tf32_rn(float x) {
    float r;
    asm("cvt.rna.tf32.f32 %0, %1;" : "=f"(r) : "f"(x));
    return r;
}
#define MBAR_INIT(addr, cnt) \
    asm volatile("mbarrier.init.shared.b64 [%0], %1;" :: "r"(addr), "r"(cnt) : "memory")
#define MBAR_WAIT(addr, par) do { \
    uint32_t _m = (addr), _p = (par), _d; \
    asm volatile("{\n\t.reg .pred p;\n\t" \
        "mbarrier.try_wait.parity.acquire.cta.shared::cta.b64 p, [%1], %2;\n\t" \
        "selp.b32 %0, 1, 0, p;\n\t}" : "=r"(_d) : "r"(_m), "r"(_p) : "memory"); \
    if (!_d) { \
        asm volatile("{\n\t.reg .pred P1;\n\tWL%=:\n\t" \
            "mbarrier.try_wait.parity.acquire.cta.shared::cta.b64 P1, [%0], %1, 0x989680;\n\t" \
            "@P1 bra.uni WD%=;\n\tbra.uni WL%=;\n\tWD%=:\n\t}" \
            :: "r"(_m), "r"(_p) : "memory"); \
    } } while (0)

#if HAS_TC
#define TC_ALLOC(smem_addr, n) \
    asm volatile("tcgen05.alloc.cta_group::1.sync.aligned.shared::cta.b32 [%0], %1;" \
        :: "r"(smem_addr), "r"(n) : "memory")
#define TC_DEALLOC(tmem, n) \
    asm volatile("tcgen05.dealloc.cta_group::1.sync.aligned.b32 %0, %1;" :: "r"(tmem), "r"(n))
#define TC_RELINQ() \
    asm volatile("tcgen05.relinquish_alloc_permit.cta_group::1.sync.aligned;")
#define TC_COMMIT(mbar) \
    asm volatile("tcgen05.commit.cta_group::1.mbarrier::arrive::one.shared::cluster.b64 [%0];" \
        :: "r"(mbar) : "memory")
#define TC_FENCE_AFTER() asm volatile("tcgen05.fence::after_thread_sync;" ::: "memory")
#define TC_FENCE_BEFORE() asm volatile("tcgen05.fence::before_thread_sync;" ::: "memory")
#define TC_WAIT_LD() asm volatile("tcgen05.wait::ld.sync.aligned;" ::: "memory")
#define LDTM_X32(r, addr) \
    asm volatile("tcgen05.ld.sync.aligned.32x32b.x32.b32 " \
        "{%0,%1,%2,%3,%4,%5,%6,%7,%8,%9,%10,%11,%12,%13,%14,%15," \
        "%16,%17,%18,%19,%20,%21,%22,%23,%24,%25,%26,%27,%28,%29,%30,%31}, [%32];" \
        : "=r"((r)[0]),"=r"((r)[1]),"=r"((r)[2]),"=r"((r)[3]), \
          "=r"((r)[4]),"=r"((r)[5]),"=r"((r)[6]),"=r"((r)[7]), \
          "=r"((r)[8]),"=r"((r)[9]),"=r"((r)[10]),"=r"((r)[11]), \
          "=r"((r)[12]),"=r"((r)[13]),"=r"((r)[14]),"=r"((r)[15]), \
          "=r"((r)[16]),"=r"((r)[17]),"=r"((r)[18]),"=r"((r)[19]), \
          "=r"((r)[20]),"=r"((r)[21]),"=r"((r)[22]),"=r"((r)[23]), \
          "=r"((r)[24]),"=r"((r)[25]),"=r"((r)[26]),"=r"((r)[27]), \
          "=r"((r)[28]),"=r"((r)[29]),"=r"((r)[30]),"=r"((r)[31]) \
        : "r"(addr))

static __device__ __forceinline__ uint64_t make_desc(uint32_t addr) {
    const uint64_t base = (uint64_t(2) << 61) | (uint64_t(1) << 46)
                        | (uint64_t(64) << 32) | (uint64_t(1) << 16);
    return base | ((uint64_t)(addr >> 4) & 0x3FFF);
}
__device__ __forceinline__ void mma_tf32(uint32_t d, uint64_t ad, uint64_t bd,
                                         uint32_t idesc, uint32_t en) {
    asm volatile("{\n\t.reg .pred p;\n\tsetp.ne.u32 p, %5, 0;\n\t"
        "tcgen05.mma.cta_group::1.kind::tf32 [%0], %1, %2, %3, {%4,%4,%4,%4}, p;\n\t}"
        :: "r"(d), "l"(ad), "l"(bd), "r"(idesc), "r"(0u), "r"(en) : "memory");
}
#endif  // HAS_TC

__device__ __forceinline__ uint32_t swz(uint32_t o) { return o ^ ((o >> 3) & 0x70); }

__device__ __forceinline__ void cp16(uint32_t dst, const void* src, bool valid) {
    int sz = valid ? 16 : 0;
    asm volatile("cp.async.cg.shared.global [%0], [%1], 16, %2;"
                 :: "r"(dst), "l"(src), "r"(sz));
}

// ---------------- transpose + tf32-RN round ----------------
__global__ void __launch_bounds__(256) k_transpose(const float* __restrict__ W) {
    __shared__ float tile[32][33];
    int k0 = (blockIdx.x & 15) * 32, m0 = (blockIdx.x >> 4) * 32;
    int x = threadIdx.x & 31, y = threadIdx.x >> 5;
    #pragma unroll
    for (int i = 0; i < 4; i++)
        tile[y + i * 8][x] = W[(size_t)(m0 + y + i * 8) * HID + k0 + x];
    __syncthreads();
    #pragma unroll
    for (int i = 0; i < 4; i++)
        g_Wt[(size_t)(k0 + y + i * 8) * 4096 + m0 + x] = tf32_rn(tile[x][y + i * 8]);
}

// ---------------- pre: a_m, fsq + per-block fp64 (sum a, sum a^2) ----------------
__global__ void __launch_bounds__(256) k_pre(const float* __restrict__ W,
                                             const float* __restrict__ F) {
    __shared__ double sda[8], sda2[8];
    int tid = threadIdx.x, wid = tid >> 5, lane = tid & 31;
    int warp = (int)blockIdx.x * 8 + wid;
    int r0 = warp * 4;
    bool isW = (r0 < MC);
    const float* base = isW ? W : F;
    int rb = isW ? r0 : (r0 - MC);
    float4 v[4][4];
    #pragma unroll
    for (int j = 0; j < 4; j++)
        #pragma unroll
        for (int q = 0; q < 4; q++)
            v[j][q] = reinterpret_cast<const float4*>(
                base + (size_t)(rb + j) * HID)[lane + q * 32];
    float acc[4];
    #pragma unroll
    for (int j = 0; j < 4; j++) {
        float a = 0.f;
        #pragma unroll
        for (int q = 0; q < 4; q++)
            a += v[j][q].x*v[j][q].x + v[j][q].y*v[j][q].y
               + v[j][q].z*v[j][q].z + v[j][q].w*v[j][q].w;
        acc[j] = a;
    }
    #pragma unroll
    for (int o = 16; o > 0; o >>= 1)
        #pragma unroll
        for (int j = 0; j < 4; j++)
            acc[j] += __shfl_down_sync(0xffffffffu, acc[j], o);
    if (lane == 0) {
        double da = 0.0, da2 = 0.0;
        #pragma unroll
        for (int j = 0; j < 4; j++) {
            if (isW) {
                g_a[r0 + j] = acc[j];
                double a = (double)acc[j];
                da += a; da2 += a * a;
            } else {
                g_fsq[rb + j] = acc[j];
            }
        }
        sda[wid] = da; sda2[wid] = da2;
    }
    __syncthreads();
    if (tid == 0) {
        double da = 0.0, da2 = 0.0;
        #pragma unroll
        for (int j = 0; j < 8; j++) { da += sda[j]; da2 += sda2[j]; }
        g_ap[blockIdx.x] = da; g_a2p[blockIdx.x] = da2;
    }
}

// ---------------- su: 128 blocks x 8 warps; 2 warps per k (half-rows) ----------
__global__ void __launch_bounds__(256) k_su() {
    __shared__ float sh_s[4][2], sh_u[4][2];
    __shared__ double sh_d[4][2];
    int tid = threadIdx.x, wid = tid >> 5, lane = tid & 31;
    int kl = wid >> 1, half = wid & 1;
    int k = (int)blockIdx.x * 4 + kl;
    const float4* row = reinterpret_cast<const float4*>(g_Wt + (size_t)k * 4096)
                      + half * 500;
    const float4* av  = reinterpret_cast<const float4*>(g_a) + half * 500;
    float s = 0.f, u = 0.f;
    #pragma unroll
    for (int q = 0; q < 16; q++) {
        int idx = lane + q * 32;
        if (idx < 500) {
            float4 w = row[idx];
            float4 a = av[idx];
            s += w.x + w.y + w.z + w.w;
            u += a.x*w.x + a.y*w.y + a.z*w.z + a.w*w.w;
        }
    }
    #pragma unroll
    for (int o = 16; o > 0; o >>= 1) {
        s += __shfl_down_sync(0xffffffffu, s, o);
        u += __shfl_down_sync(0xffffffffu, u, o);
    }
    if (lane == 0) { sh_s[kl][half] = s; sh_u[kl][half] = u; }
    __syncthreads();
    if (tid < 4) {
        float sk = sh_s[tid][0] + sh_s[tid][1];
        float uk = sh_u[tid][0] + sh_u[tid][1];
        sh_d[tid][0] = (double)sk * (double)sk;
        sh_d[tid][1] = (double)uk * (double)sk;
    }
    __syncthreads();
    if (tid == 0) {
        double s2 = 0.0, us = 0.0;
        #pragma unroll
        for (int j = 0; j < 4; j++) { s2 += sh_d[j][0]; us += sh_d[j][1]; }
        g_s2p[blockIdx.x] = s2; g_usp[blockIdx.x] = us;
    }
}

// ---------------- pipeline layout ----------------
#define STG       4
#define STG_BYTES 16384
#define OFF_A     1024
#define OFF_B     (1024 + STG*STG_BYTES)
#define SMEM_TC   (1024 + 2*STG*STG_BYTES)
#define IDESC_TF32 ((1u<<4) | (2u<<7) | (2u<<10) | (16u<<17) | (8u<<24))
#define KC      32
#define NCHUNK  16

#if HAS_TC
// 256-thread load: 1024 (row,seg) pairs, 4 per thread, A+B
__device__ __forceinline__ void gram_load_chunk(uint32_t sb, int stage, int c,
                                                int K0, int L0, int mbase, int tid) {
    int moff = mbase + c * 32;
    uint32_t dA = sb + OFF_A + stage * STG_BYTES;
    uint32_t dB = sb + OFF_B + stage * STG_BYTES;
    #pragma unroll
    for (int p = 0; p < 4; p++) {
        int idx = p * 256 + tid;
        int r = idx >> 3, seg = idx & 7;
        uint32_t off = swz((uint32_t)(r * 128 + seg * 16));
        cp16(dA + off, g_Wt + (size_t)(K0 + r) * 4096 + moff + seg * 4, true);
        cp16(dB + off, g_Wt + (size_t)(L0 + r) * 4096 + moff + seg * 4, true);
    }
}
__device__ __forceinline__ void fw_load_chunk(uint32_t sb, int stage, int c,
                                              const float* __restrict__ W,
                                              const float* __restrict__ F,
                                              int m0, int b0, int tid) {
    int kc = c * KC;
    uint32_t dA = sb + OFF_A + stage * STG_BYTES;
    uint32_t dB = sb + OFF_B + stage * STG_BYTES;
    #pragma unroll
    for (int p = 0; p < 4; p++) {
        int idx = p * 256 + tid;
        int r = idx >> 3, seg = idx & 7;
        uint32_t off = swz((uint32_t)(r * 128 + seg * 16));
        int m = m0 + r;
        bool v = (m < MC);
        cp16(dA + off, W + (size_t)(v ? m : 0) * HID + kc + seg * 4, v);
        cp16(dB + off, F + (size_t)(b0 + r) * HID + kc + seg * 4, true);
    }
}
#endif

// gram: grid 100 = 10 tiles x 10 z (z<5: 13 chunks of 32; z>=5: 12)
__global__ void __launch_bounds__(256, 1) k_gram_tc() {
    int tid = threadIdx.x, wid = tid >> 5, lane = tid & 31;
    int t = blockIdx.x / 10, z = blockIdx.x % 10;
    int K0 = c_ti[t] * 128, L0 = c_tj[t] * 128;
    int mbase = (z < 5) ? z * 416 : 2080 + (z - 5) * 384;
    int nch = (z < 5) ? 13 : 12;
#if HAS_TC
    extern __shared__ char smem[];
    uint32_t sb = smem_u32(smem);

    if (tid < 4) MBAR_INIT(sb + tid * 8, 1);
    if (wid == 0) { TC_ALLOC(sb + 32, 128); TC_RELINQ(); }
    __syncthreads();
    uint32_t tmem;
    asm volatile("ld.shared.b32 %0, [%1];" : "=r"(tmem) : "r"(sb + 32));

    #pragma unroll
    for (int c0 = 0; c0 < 3; c0++) {
        gram_load_chunk(sb, c0, c0, K0, L0, mbase, tid);
        asm volatile("cp.async.commit_group;" ::: "memory");
    }
    uint32_t phv = 0;
    for (int c = 0; c < nch; c++) {
        int s = c & 3;
        if (c + 3 < nch) {
            int so = (c + 3) & 3;
            if (c >= 1) {
                MBAR_WAIT(sb + so * 8, (phv >> so) & 1u);
                phv ^= (1u << so);
            }
            gram_load_chunk(sb, so, c + 3, K0, L0, mbase, tid);
        }
        asm volatile("cp.async.commit_group;" ::: "memory");
        asm volatile("cp.async.wait_group 3;" ::: "memory");
        __syncthreads();
        if (wid == 0 && elect_one()) {
            asm volatile("fence.proxy.async.shared::cta;" ::: "memory");
            uint64_t ad = make_desc(sb + OFF_A + s * STG_BYTES);
            uint64_t bd = make_desc(sb + OFF_B + s * STG_BYTES);
            #pragma unroll
            for (int k = 0; k < 4; k++)
                mma_tf32(tmem, ad + k * 2, bd + k * 2, IDESC_TF32,
                         (c > 0 || k > 0) ? 1u : 0u);
            TC_COMMIT(sb + s * 8);
        }
    }
    __syncthreads();
    {
        int so = (nch - 1) & 3;
        MBAR_WAIT(sb + so * 8, (phv >> so) & 1u);
    }
    TC_FENCE_AFTER();

    float* dst = g_G2 + ((size_t)blockIdx.x << 14);
    int row = (wid & 3) * 32 + lane;
    int cb = (wid >> 2) * 64;        // warps 0-3: cols 0-63; warps 4-7: 64-127
    #pragma unroll
    for (int j0 = 0; j0 < 64; j0 += 32) {
        uint32_t r[32];
        LDTM_X32(r, tmem + cb + j0);
        TC_WAIT_LD();
        #pragma unroll
        for (int j4 = 0; j4 < 8; j4++) {
            float4 v = make_float4(__uint_as_float(r[j4*4+0]), __uint_as_float(r[j4*4+1]),
                                   __uint_as_float(r[j4*4+2]), __uint_as_float(r[j4*4+3]));
            *reinterpret_cast<float4*>(&dst[(size_t)row * 128 + cb + j0 + j4 * 4]) = v;
        }
    }
    TC_FENCE_BEFORE();
    __syncthreads();
    if (wid == 0) TC_DEALLOC(tmem, 128);
#else
    float* dst = g_G2 + ((size_t)blockIdx.x << 14);
    int len = nch * 32;
    for (int e = tid; e < 16384; e += blockDim.x) {
        int k = K0 + (e >> 7), l = L0 + (e & 127);
        float acc = 0.f;
        for (int m = 0; m < len; m++)
            acc = fmaf(g_Wt[(size_t)k * 4096 + mbase + m],
                       g_Wt[(size_t)l * 4096 + mbase + m], acc);
        dst[e] = acc;
    }
#endif
}

__global__ void __launch_bounds__(256, 1) k_fw_tc(const float* __restrict__ F,
                                                  const float* __restrict__ W,
                                                  float* __restrict__ out) {
#if HAS_TC
    extern __shared__ char smem[];
    uint32_t sb = smem_u32(smem);
    int tid = threadIdx.x, wid = tid >> 5, lane = tid & 31;
    int m0 = (int)blockIdx.x * 128, b0 = (int)blockIdx.y * 128;

    if (tid < 4) MBAR_INIT(sb + tid * 8, 1);
    if (wid == 0) { TC_ALLOC(sb + 32, 128); TC_RELINQ(); }
    __syncthreads();
    uint32_t tmem;
    asm volatile("ld.shared.b32 %0, [%1];" : "=r"(tmem) : "r"(sb + 32));

    #pragma unroll
    for (int c0 = 0; c0 < 3; c0++) {
        fw_load_chunk(sb, c0, c0, W, F, m0, b0, tid);
        asm volatile("cp.async.commit_group;" ::: "memory");
    }
    uint32_t phv = 0;
    for (int c = 0; c < NCHUNK; c++) {
        int s = c & 3;
        if (c + 3 < NCHUNK) {
            int so = (c + 3) & 3;
            if (c >= 1) {
                MBAR_WAIT(sb + so * 8, (phv >> so) & 1u);
                phv ^= (1u << so);
            }
            fw_load_chunk(sb, so, c + 3, W, F, m0, b0, tid);
        }
        asm volatile("cp.async.commit_group;" ::: "memory");
        asm volatile("cp.async.wait_group 3;" ::: "memory");
        __syncthreads();
        if (wid == 0 && elect_one()) {
            asm volatile("fence.proxy.async.shared::cta;" ::: "memory");
            uint64_t ad = make_desc(sb + OFF_A + s * STG_BYTES);
            uint64_t bd = make_desc(sb + OFF_B + s * STG_BYTES);
            #pragma unroll
            for (int k = 0; k < 4; k++)
                mma_tf32(tmem, ad + k * 2, bd + k * 2, IDESC_TF32,
                         (c > 0 || k > 0) ? 1u : 0u);
            TC_COMMIT(sb + s * 8);
        }
    }
    __syncthreads();
    MBAR_WAIT(sb + 3 * 8, (phv >> 3) & 1u);
    TC_FENCE_AFTER();

    // epilogue: warps 0-3 -> cols 0-63, warps 4-7 -> cols 64-127
    int m = m0 + (wid & 3) * 32 + lane;
    int cb = (wid >> 2) * 64;
    float a = (m < MC) ? __ldg(&g_a[m]) : __int_as_float(0x7f800000);
    int grp = m >> 2;
    #pragma unroll
    for (int j0 = 0; j0 < 64; j0 += 32) {
        uint32_t r[32];
        LDTM_X32(r, tmem + cb + j0);
        TC_WAIT_LD();
        #pragma unroll
        for (int jj = 0; jj < 32; jj++) {
            float fw = __uint_as_float(r[jj]);
            float x = fmaf(-2.f, fw, a);
            x = fminf(x, __shfl_xor_sync(0xffffffffu, x, 1));
            x = fminf(x, __shfl_xor_sync(0xffffffffu, x, 2));
            if ((lane & 3) == 0 && m < MC) {
                int b = b0 + cb + j0 + jj;
                out[(size_t)b * (NCLS + 1) + grp] =
                    expf(-(__ldg(&g_fsq[b]) + x) * INV_SIGMA);
            }
        }
    }
    TC_FENCE_BEFORE();
    __syncthreads();
    if (wid == 0) TC_DEALLOC(tmem, 128);
#else
    int tid = threadIdx.x;
    int m0 = (int)blockIdx.x * 128, b0 = (int)blockIdx.y * 128;
    int m = m0 + (tid & 127);
    if (m >= MC || tid >= 128) return;
    float a = g_a[m];
    int grp = m >> 2;
    const float* wrow = W + (size_t)m * HID;
    for (int jb = 0; jb < 128; jb++) {
        int b = b0 + jb;
        const float* frow = F + (size_t)b * HID;
        float dot = 0.f;
        for (int k = 0; k < HID; k++) dot = fmaf(wrow[k], frow[k], dot);
        float x = fmaf(-2.f, dot, a);
        x = fminf(x, __shfl_xor_sync(0xffffffffu, x, 1));
        x = fminf(x, __shfl_xor_sync(0xffffffffu, x, 2));
        if ((tid & 3) == 0)
            out[(size_t)b * (NCLS + 1) + grp] =
                expf(-(g_fsq[b] + x) * INV_SIGMA);
    }
#endif
}

// ---------------- f2 + fused finalize (last-arriving block) ----------------
__global__ void __launch_bounds__(256) k_f2fin(float* __restrict__ out) {
    __shared__ double sd[8], sd2[8], sd3[8], sd4[8], sd5[8];
    __shared__ bool is_last;
    __shared__ float rw_s;
    int tid = threadIdx.x, wid = tid >> 5, lane = tid & 31;

    double acc = 0.0;
    for (int i = (int)blockIdx.x * 256 + tid; i < 10 * 16384; i += 160 * 256) {
        int t = i >> 14, e = i & 16383;
        float g = 0.f;
        #pragma unroll
        for (int z = 0; z < 10; z++) g += g_G2[((size_t)(t * 10 + z) << 14) + e];
        double w = (c_ti[t] == c_tj[t]) ? 1.0 : 2.0;
        acc += w * (double)g * (double)g;
    }
    #pragma unroll
    for (int o = 16; o > 0; o >>= 1)
        acc += __shfl_down_sync(0xffffffffu, acc, o);
    if (lane == 0) sd[wid] = acc;
    __syncthreads();
    if (tid == 0) {
        double f = 0.0;
        #pragma unroll
        for (int j = 0; j < 8; j++) f += sd[j];
        g_f2p[blockIdx.x] = f;
    }
    __threadfence();
    __syncthreads();
    if (tid == 0) {
        unsigned v = atomicAdd(&g_ctr, 1u);
        is_last = (v == 159u);
    }
    __syncthreads();
    if (!is_last) return;
    if (tid == 0) g_ctr = 0;
    __threadfence();

    double la  = (tid < 141) ? g_ap[tid]  : 0.0;
    double la2 = (tid < 141) ? g_a2p[tid] : 0.0;
    double ls2 = (tid < 128) ? g_s2p[tid] : 0.0;
    double lus = (tid < 128) ? g_usp[tid] : 0.0;
    double lf2 = (tid < 160) ? g_f2p[tid] : 0.0;
    #pragma unroll
    for (int o = 16; o > 0; o >>= 1) {
        la  += __shfl_down_sync(0xffffffffu, la,  o);
        la2 += __shfl_down_sync(0xffffffffu, la2, o);
        ls2 += __shfl_down_sync(0xffffffffu, ls2, o);
        lus += __shfl_down_sync(0xffffffffu, lus, o);
        lf2 += __shfl_down_sync(0xffffffffu, lf2, o);
    }
    if (lane == 0) { sd[wid]=la; sd2[wid]=la2; sd3[wid]=ls2; sd4[wid]=lus; sd5[wid]=lf2; }
    __syncthreads();
    if (tid == 0) {
        double sum_a=0, sum_a2=0, s2=0, sum_at=0, F2=0;
        #pragma unroll
        for (int j = 0; j < 8; j++) {
            sum_a += sd[j]; sum_a2 += sd2[j]; s2 += sd3[j];
            sum_at += sd4[j]; F2 += sd5[j];
        }
        double mc = (double)MC;
        double denom = 2.0 / (mc * mc - mc);
        double S1 = mc * sum_a - s2;
        double mu = denom * S1;
        double S2 = mc * sum_a2 + sum_a * sum_a + 2.0 * F2 - 4.0 * sum_at;
        rw_s = (float)(denom * S2 - mu * mu);
    }
    __syncthreads();
    #pragma unroll
    for (int j = 0; j < 2; j++)
        out[(size_t)(tid * 2 + j) * (NCLS + 1) + NCLS] = rw_s;
}

extern "C" void kernel_launch(void* const* d_in, const int* in_sizes, int n_in,
                              void* d_out, int out_size) {
    const float* F = (const float*)d_in[0];   // [512,512]
    const float* W = (const float*)d_in[1];   // [4000,512]
    float* out = (float*)d_out;               // [512,1001]
    (void)in_sizes; (void)n_in; (void)out_size;

    static bool inited = false;
    static cudaStream_t s1, s2;
    static cudaEvent_t evA, evT, evP, evS, evB;
    if (!inited) {
        cudaFuncSetAttribute(k_fw_tc, cudaFuncAttributeMaxDynamicSharedMemorySize,
                             SMEM_TC);
        cudaFuncSetAttribute(k_gram_tc, cudaFuncAttributeMaxDynamicSharedMemorySize,
                             SMEM_TC);
        cudaStreamCreateWithFlags(&s1, cudaStreamNonBlocking);
        cudaStreamCreateWithFlags(&s2, cudaStreamNonBlocking);
        cudaEventCreateWithFlags(&evA, cudaEventDisableTiming);
        cudaEventCreateWithFlags(&evT, cudaEventDisableTiming);
        cudaEventCreateWithFlags(&evP, cudaEventDisableTiming);
        cudaEventCreateWithFlags(&evS, cudaEventDisableTiming);
        cudaEventCreateWithFlags(&evB, cudaEventDisableTiming);
        inited = true;
    }

    // fork
    cudaEventRecord(evA, 0);
    cudaStreamWaitEvent(s1, evA, 0);

    // chain 0 (default): transpose -> gram
    k_transpose<<<2000, 256>>>(W);
    cudaEventRecord(evT, 0);                  // Wt ready
    k_gram_tc<<<100, 256, SMEM_TC>>>();

    // chain 1 (s1): pre -> fw
    k_pre<<<141, 256, 0, s1>>>(W, F);
    cudaEventRecord(evP, s1);
    k_fw_tc<<<dim3(32, 4), 256, SMEM_TC, s1>>>(F, W, out);
    cudaEventRecord(evB, s1);

    // chain 2 (s2): su (needs Wt + a) — off the critical path
    cudaStreamWaitEvent(s2, evT, 0);
    cudaStreamWaitEvent(s2, evP, 0);
    k_su<<<128, 256, 0, s2>>>();
    cudaEventRecord(evS, s2);

    // join: f2 + fused finalize
    cudaStreamWaitEvent(0, evB, 0);
    cudaStreamWaitEvent(0, evS, 0);
    k_f2fin<<<160, 256>>>(out);
}

// round 14
// speedup vs baseline: 1.6545x; 1.0571x over previous
#include <cuda_runtime.h>
#include <math.h>
#include <stdint.h>

#define BATCH 512
#define HID   512
#define NCLS  1000
#define MC    4000
#define INV_SIGMA (1.0f/10.0f)

#if defined(__CUDA_ARCH__) && (__CUDA_ARCH__ == 1030) && defined(__CUDA_ARCH_FEAT_SM103_ALL)
#define HAS_TC 1
#else
#define HAS_TC 0
#endif

// ---------------- scratch ----------------
__device__ __align__(16) float g_a[4096];        // ||w_m||^2 (exact fp32)
__device__ __align__(16) float g_fsq[BATCH];     // ||f_b||^2
__device__ __align__(16) float g_Wt[512*4096];   // W^T, tf32-RN-rounded, stride 4096
__device__ __align__(16) float g_G2[100*16384];  // Gram partials: 10 tiles x 10 z
__device__ double g_ap[141], g_a2p[141];         // per-block sum a, sum a^2
__device__ double g_s2p[128], g_usp[128];        // per-block sum s^2, sum u*s
__device__ double g_f2p[160];                    // per-block F2 partials
__device__ unsigned g_ctr = 0;                   // arrival counter (reset each run)

__constant__ int c_ti[10] = {0,0,0,0,1,1,1,2,2,3};
__constant__ int c_tj[10] = {0,1,2,3,1,2,3,2,3,3};

// ---------------- PTX helpers ----------------
__device__ __forceinline__ uint32_t smem_u32(const void* p) {
    uint32_t a;
    asm("{ .reg .u64 t; cvta.to.shared.u64 t, %1; cvt.u32.u64 %0, t; }"
        : "=r"(a) : "l"(p));
    return a;
}
__device__ __forceinline__ uint32_t elect_one() {
    uint32_t pred;
    asm volatile("{\n\t.reg .pred p;\n\telect.sync _|p, 0xFFFFFFFF;\n\t"
                 "selp.b32 %0, 1, 0, p;\n\t}" : "=r"(pred));
    return pred;
}
__device__ __forceinline__ float tf32_rn(float x) {
    float r;
    asm("cvt.rna.tf32.f32 %0, %1;" : "=f"(r) : "f"(x));
    return r;
}
#define MBAR_INIT(addr, cnt) \
    asm volatile("mbarrier.init.shared.b64 [%0], %1;" :: "r"(addr), "r"(cnt) : "memory")
#define MBAR_WAIT(addr, par) do { \
    uint32_t _m = (addr), _p = (par), _d; \
    asm volatile("{\n\t.reg .pred p;\n\t" \
        "mbarrier.try_wait.parity.acquire.cta.shared::cta.b64 p, [%1], %2;\n\t" \
        "selp.b32 %0, 1, 0, p;\n\t}" : "=r"(_d) : "r"(_m), "r"(_p) : "memory"); \
    if (!_d) { \
        asm volatile("{\n\t.reg .pred P1;\n\tWL%=:\n\t" \
            "mbarrier.try_wait.parity.acquire.cta.shared::cta.b64 P1, [%0], %1, 0x989680;\n\t" \
            "@P1 bra.uni WD%=;\n\tbra.uni WL%=;\n\tWD%=:\n\t}" \
            :: "r"(_m), "r"(_p) : "memory"); \
    } } while (0)

#if HAS_TC
#define TC_ALLOC(smem_addr, n) \
    asm volatile("tcgen05.alloc.cta_group::1.sync.aligned.shared::cta.b32 [%0], %1;" \
        :: "r"(smem_addr), "r"(n) : "memory")
#define TC_DEALLOC(tmem, n) \
    asm volatile("tcgen05.dealloc.cta_group::1.sync.aligned.b32 %0, %1;" :: "r"(tmem), "r"(n))
#define TC_RELINQ() \
    asm volatile("tcgen05.relinquish_alloc_permit.cta_group::1.sync.aligned;")
#define TC_COMMIT(mbar) \
    asm volatile("tcgen05.commit.cta_group::1.mbarrier::arrive::one.shared::cluster.b64 [%0];" \
        :: "r"(mbar) : "memory")
#define TC_FENCE_AFTER() asm volatile("tcgen05.fence::after_thread_sync;" ::: "memory")
#define TC_FENCE_BEFORE() asm volatile("tcgen05.fence::before_thread_sync;" ::: "memory")
#define TC_WAIT_LD() asm volatile("tcgen05.wait::ld.sync.aligned;" ::: "memory")
#define LDTM_X32(r, addr) \
    asm volatile("tcgen05.ld.sync.aligned.32x32b.x32.b32 " \
        "{%0,%1,%2,%3,%4,%5,%6,%7,%8,%9,%10,%11,%12,%13,%14,%15," \
        "%16,%17,%18,%19,%20,%21,%22,%23,%24,%25,%26,%27,%28,%29,%30,%31}, [%32];" \
        : "=r"((r)[0]),"=r"((r)[1]),"=r"((r)[2]),"=r"((r)[3]), \
          "=r"((r)[4]),"=r"((r)[5]),"=r"((r)[6]),"=r"((r)[7]), \
          "=r"((r)[8]),"=r"((r)[9]),"=r"((r)[10]),"=r"((r)[11]), \
          "=r"((r)[12]),"=r"((r)[13]),"=r"((r)[14]),"=r"((r)[15]), \
          "=r"((r)[16]),"=r"((r)[17]),"=r"((r)[18]),"=r"((r)[19]), \
          "=r"((r)[20]),"=r"((r)[21]),"=r"((r)[22]),"=r"((r)[23]), \
          "=r"((r)[24]),"=r"((r)[25]),"=r"((r)[26]),"=r"((r)[27]), \
          "=r"((r)[28]),"=r"((r)[29]),"=r"((r)[30]),"=r"((r)[31]) \
        : "r"(addr))

static __device__ __forceinline__ uint64_t make_desc(uint32_t addr) {
    const uint64_t base = (uint64_t(2) << 61) | (uint64_t(1) << 46)
                        | (uint64_t(64) << 32) | (uint64_t(1) << 16);
    return base | ((uint64_t)(addr >> 4) & 0x3FFF);
}
__device__ __forceinline__ void mma_tf32(uint32_t d, uint64_t ad, uint64_t bd,
                                         uint32_t idesc, uint32_t en) {
    asm volatile("{\n\t.reg .pred p;\n\tsetp.ne.u32 p, %5, 0;\n\t"
        "tcgen05.mma.cta_group::1.kind::tf32 [%0], %1, %2, %3, {%4,%4,%4,%4}, p;\n\t}"
        :: "r"(d), "l"(ad), "l"(bd), "r"(idesc), "r"(0u), "r"(en) : "memory");
}
#endif  // HAS_TC

__device__ __forceinline__ uint32_t swz(uint32_t o) { return o ^ ((o >> 3) & 0x70); }

__device__ __forceinline__ void cp16(uint32_t dst, const void* src, bool valid) {
    int sz = valid ? 16 : 0;
    asm volatile("cp.async.cg.shared.global [%0], [%1], 16, %2;"
                 :: "r"(dst), "l"(src), "r"(sz));
}

// ---------------- transpose + tf32-RN round ----------------
__global__ void __launch_bounds__(256) k_transpose(const float* __restrict__ W) {
    __shared__ float tile[32][33];
    int k0 = (blockIdx.x & 15) * 32, m0 = (blockIdx.x >> 4) * 32;
    int x = threadIdx.x & 31, y = threadIdx.x >> 5;
    #pragma unroll
    for (int i = 0; i < 4; i++)
        tile[y + i * 8][x] = W[(size_t)(m0 + y + i * 8) * HID + k0 + x];
    __syncthreads();
    #pragma unroll
    for (int i = 0; i < 4; i++)
        g_Wt[(size_t)(k0 + y + i * 8) * 4096 + m0 + x] = tf32_rn(tile[x][y + i * 8]);
}

// ---------------- pre: a_m, fsq + per-block fp64 (sum a, sum a^2) ----------------
__global__ void __launch_bounds__(256) k_pre(const float* __restrict__ W,
                                             const float* __restrict__ F) {
    __shared__ double sda[8], sda2[8];
    int tid = threadIdx.x, wid = tid >> 5, lane = tid & 31;
    int warp = (int)blockIdx.x * 8 + wid;
    int r0 = warp * 4;
    bool isW = (r0 < MC);
    const float* base = isW ? W : F;
    int rb = isW ? r0 : (r0 - MC);
    float4 v[4][4];
    #pragma unroll
    for (int j = 0; j < 4; j++)
        #pragma unroll
        for (int q = 0; q < 4; q++)
            v[j][q] = reinterpret_cast<const float4*>(
                base + (size_t)(rb + j) * HID)[lane + q * 32];
    float acc[4];
    #pragma unroll
    for (int j = 0; j < 4; j++) {
        float a = 0.f;
        #pragma unroll
        for (int q = 0; q < 4; q++)
            a += v[j][q].x*v[j][q].x + v[j][q].y*v[j][q].y
               + v[j][q].z*v[j][q].z + v[j][q].w*v[j][q].w;
        acc[j] = a;
    }
    #pragma unroll
    for (int o = 16; o > 0; o >>= 1)
        #pragma unroll
        for (int j = 0; j < 4; j++)
            acc[j] += __shfl_down_sync(0xffffffffu, acc[j], o);
    if (lane == 0) {
        double da = 0.0, da2 = 0.0;
        #pragma unroll
        for (int j = 0; j < 4; j++) {
            if (isW) {
                g_a[r0 + j] = acc[j];
                double a = (double)acc[j];
                da += a; da2 += a * a;
            } else {
                g_fsq[rb + j] = acc[j];
            }
        }
        sda[wid] = da; sda2[wid] = da2;
    }
    __syncthreads();
    if (tid == 0) {
        double da = 0.0, da2 = 0.0;
        #pragma unroll
        for (int j = 0; j < 8; j++) { da += sda[j]; da2 += sda2[j]; }
        g_ap[blockIdx.x] = da; g_a2p[blockIdx.x] = da2;
    }
}

// ---------------- su: 128 blocks x 8 warps; 2 warps per k (half-rows) ----------
__global__ void __launch_bounds__(256) k_su() {
    __shared__ float sh_s[4][2], sh_u[4][2];
    __shared__ double sh_d[4][2];
    int tid = threadIdx.x, wid = tid >> 5, lane = tid & 31;
    int kl = wid >> 1, half = wid & 1;
    int k = (int)blockIdx.x * 4 + kl;
    const float4* row = reinterpret_cast<const float4*>(g_Wt + (size_t)k * 4096)
                      + half * 500;
    const float4* av  = reinterpret_cast<const float4*>(g_a) + half * 500;
    float s = 0.f, u = 0.f;
    #pragma unroll
    for (int q = 0; q < 16; q++) {
        int idx = lane + q * 32;
        if (idx < 500) {
            float4 w = row[idx];
            float4 a = av[idx];
            s += w.x + w.y + w.z + w.w;
            u += a.x*w.x + a.y*w.y + a.z*w.z + a.w*w.w;
        }
    }
    #pragma unroll
    for (int o = 16; o > 0; o >>= 1) {
        s += __shfl_down_sync(0xffffffffu, s, o);
        u += __shfl_down_sync(0xffffffffu, u, o);
    }
    if (lane == 0) { sh_s[kl][half] = s; sh_u[kl][half] = u; }
    __syncthreads();
    if (tid < 4) {
        float sk = sh_s[tid][0] + sh_s[tid][1];
        float uk = sh_u[tid][0] + sh_u[tid][1];
        sh_d[tid][0] = (double)sk * (double)sk;
        sh_d[tid][1] = (double)uk * (double)sk;
    }
    __syncthreads();
    if (tid == 0) {
        double s2 = 0.0, us = 0.0;
        #pragma unroll
        for (int j = 0; j < 4; j++) { s2 += sh_d[j][0]; us += sh_d[j][1]; }
        g_s2p[blockIdx.x] = s2; g_usp[blockIdx.x] = us;
    }
}

// ---------------- pipeline layout: 3 stages -> 2 CTAs/SM ----------------
#define STG       3
#define STG_BYTES 16384
#define OFF_A     1024
#define OFF_B     (1024 + STG*STG_BYTES)
#define SMEM_TC   (1024 + 2*STG*STG_BYTES)     // 99,328 B -> 2 CTAs/SM
#define IDESC_TF32 ((1u<<4) | (2u<<7) | (2u<<10) | (16u<<17) | (8u<<24))
#define KC      32
#define NCHUNK  16

#if HAS_TC
__device__ __forceinline__ void gram_load_chunk(uint32_t sb, int stage, int c,
                                                int K0, int L0, int mbase, int tid) {
    int moff = mbase + c * 32;
    uint32_t dA = sb + OFF_A + stage * STG_BYTES;
    uint32_t dB = sb + OFF_B + stage * STG_BYTES;
    #pragma unroll
    for (int p = 0; p < 4; p++) {
        int idx = p * 256 + tid;
        int r = idx >> 3, seg = idx & 7;
        uint32_t off = swz((uint32_t)(r * 128 + seg * 16));
        cp16(dA + off, g_Wt + (size_t)(K0 + r) * 4096 + moff + seg * 4, true);
        cp16(dB + off, g_Wt + (size_t)(L0 + r) * 4096 + moff + seg * 4, true);
    }
}
__device__ __forceinline__ void fw_load_chunk(uint32_t sb, int stage, int c,
                                              const float* __restrict__ W,
                                              const float* __restrict__ F,
                                              int m0, int b0, int tid) {
    int kc = c * KC;
    uint32_t dA = sb + OFF_A + stage * STG_BYTES;
    uint32_t dB = sb + OFF_B + stage * STG_BYTES;
    #pragma unroll
    for (int p = 0; p < 4; p++) {
        int idx = p * 256 + tid;
        int r = idx >> 3, seg = idx & 7;
        uint32_t off = swz((uint32_t)(r * 128 + seg * 16));
        int m = m0 + r;
        bool v = (m < MC);
        cp16(dA + off, W + (size_t)(v ? m : 0) * HID + kc + seg * 4, v);
        cp16(dB + off, F + (size_t)(b0 + r) * HID + kc + seg * 4, true);
    }
}
#endif

// gram: grid 100 = 10 tiles x 10 z (z<5: 13 chunks of 32; z>=5: 12)
__global__ void __launch_bounds__(256, 2) k_gram_tc() {
    int tid = threadIdx.x, wid = tid >> 5, lane = tid & 31;
    int t = blockIdx.x / 10, z = blockIdx.x % 10;
    int K0 = c_ti[t] * 128, L0 = c_tj[t] * 128;
    int mbase = (z < 5) ? z * 416 : 2080 + (z - 5) * 384;
    int nch = (z < 5) ? 13 : 12;
#if HAS_TC
    extern __shared__ char smem[];
    uint32_t sb = smem_u32(smem);

    if (tid < 3) MBAR_INIT(sb + tid * 8, 1);
    if (wid == 0) { TC_ALLOC(sb + 32, 128); TC_RELINQ(); }
    __syncthreads();
    uint32_t tmem;
    asm volatile("ld.shared.b32 %0, [%1];" : "=r"(tmem) : "r"(sb + 32));

    #pragma unroll
    for (int c0 = 0; c0 < 2; c0++) {
        gram_load_chunk(sb, c0, c0, K0, L0, mbase, tid);
        asm volatile("cp.async.commit_group;" ::: "memory");
    }
    uint32_t phv = 0;
    for (int c = 0; c < nch; c++) {
        int s = c % 3;
        if (c + 2 < nch) {
            int so = (c + 2) % 3;
            if (c >= 1) {
                MBAR_WAIT(sb + so * 8, (phv >> so) & 1u);
                phv ^= (1u << so);
            }
            gram_load_chunk(sb, so, c + 2, K0, L0, mbase, tid);
        }
        asm volatile("cp.async.commit_group;" ::: "memory");
        asm volatile("cp.async.wait_group 2;" ::: "memory");
        __syncthreads();
        if (wid == 0 && elect_one()) {
            asm volatile("fence.proxy.async.shared::cta;" ::: "memory");
            uint64_t ad = make_desc(sb + OFF_A + s * STG_BYTES);
            uint64_t bd = make_desc(sb + OFF_B + s * STG_BYTES);
            #pragma unroll
            for (int k = 0; k < 4; k++)
                mma_tf32(tmem, ad + k * 2, bd + k * 2, IDESC_TF32,
                         (c > 0 || k > 0) ? 1u : 0u);
            TC_COMMIT(sb + s * 8);
        }
    }
    __syncthreads();
    {
        int so = (nch - 1) % 3;
        MBAR_WAIT(sb + so * 8, (phv >> so) & 1u);
    }
    TC_FENCE_AFTER();

    float* dst = g_G2 + ((size_t)blockIdx.x << 14);
    int row = (wid & 3) * 32 + lane;
    int cb = (wid >> 2) * 64;
    #pragma unroll
    for (int j0 = 0; j0 < 64; j0 += 32) {
        uint32_t r[32];
        LDTM_X32(r, tmem + cb + j0);
        TC_WAIT_LD();
        #pragma unroll
        for (int j4 = 0; j4 < 8; j4++) {
            float4 v = make_float4(__uint_as_float(r[j4*4+0]), __uint_as_float(r[j4*4+1]),
                                   __uint_as_float(r[j4*4+2]), __uint_as_float(r[j4*4+3]));
            *reinterpret_cast<float4*>(&dst[(size_t)row * 128 + cb + j0 + j4 * 4]) = v;
        }
    }
    TC_FENCE_BEFORE();
    __syncthreads();
    if (wid == 0) TC_DEALLOC(tmem, 128);
#else
    float* dst = g_G2 + ((size_t)blockIdx.x << 14);
    int len = nch * 32;
    for (int e = tid; e < 16384; e += blockDim.x) {
        int k = K0 + (e >> 7), l = L0 + (e & 127);
        float acc = 0.f;
        for (int m = 0; m < len; m++)
            acc = fmaf(g_Wt[(size_t)k * 4096 + mbase + m],
                       g_Wt[(size_t)l * 4096 + mbase + m], acc);
        dst[e] = acc;
    }
#endif
}

__global__ void __launch_bounds__(256, 2) k_fw_tc(const float* __restrict__ F,
                                                  const float* __restrict__ W,
                                                  float* __restrict__ out) {
#if HAS_TC
    extern __shared__ char smem[];
    uint32_t sb = smem_u32(smem);
    int tid = threadIdx.x, wid = tid >> 5, lane = tid & 31;
    int m0 = (int)blockIdx.x * 128, b0 = (int)blockIdx.y * 128;

    if (tid < 3) MBAR_INIT(sb + tid * 8, 1);
    if (wid == 0) { TC_ALLOC(sb + 32, 128); TC_RELINQ(); }
    __syncthreads();
    uint32_t tmem;
    asm volatile("ld.shared.b32 %0, [%1];" : "=r"(tmem) : "r"(sb + 32));

    #pragma unroll
    for (int c0 = 0; c0 < 2; c0++) {
        fw_load_chunk(sb, c0, c0, W, F, m0, b0, tid);
        asm volatile("cp.async.commit_group;" ::: "memory");
    }
    uint32_t phv = 0;
    for (int c = 0; c < NCHUNK; c++) {
        int s = c % 3;
        if (c + 2 < NCHUNK) {
            int so = (c + 2) % 3;
            if (c >= 1) {
                MBAR_WAIT(sb + so * 8, (phv >> so) & 1u);
                phv ^= (1u << so);
            }
            fw_load_chunk(sb, so, c + 2, W, F, m0, b0, tid);
        }
        asm volatile("cp.async.commit_group;" ::: "memory");
        asm volatile("cp.async.wait_group 2;" ::: "memory");
        __syncthreads();
        if (wid == 0 && elect_one()) {
            asm volatile("fence.proxy.async.shared::cta;" ::: "memory");
            uint64_t ad = make_desc(sb + OFF_A + s * STG_BYTES);
            uint64_t bd = make_desc(sb + OFF_B + s * STG_BYTES);
            #pragma unroll
            for (int k = 0; k < 4; k++)
                mma_tf32(tmem, ad + k * 2, bd + k * 2, IDESC_TF32,
                         (c > 0 || k > 0) ? 1u : 0u);
            TC_COMMIT(sb + s * 8);
        }
    }
    __syncthreads();
    {
        int so = (NCHUNK - 1) % 3;
        MBAR_WAIT(sb + so * 8, (phv >> so) & 1u);
    }
    TC_FENCE_AFTER();

    // epilogue: warps 0-3 -> cols 0-63, warps 4-7 -> cols 64-127
    int m = m0 + (wid & 3) * 32 + lane;
    int cb = (wid >> 2) * 64;
    float a = (m < MC) ? __ldg(&g_a[m]) : __int_as_float(0x7f800000);
    int grp = m >> 2;
    #pragma unroll
    for (int j0 = 0; j0 < 64; j0 += 32) {
        uint32_t r[32];
        LDTM_X32(r, tmem + cb + j0);
        TC_WAIT_LD();
        #pragma unroll
        for (int jj = 0; jj < 32; jj++) {
            float fw = __uint_as_float(r[jj]);
            float x = fmaf(-2.f, fw, a);
            x = fminf(x, __shfl_xor_sync(0xffffffffu, x, 1));
            x = fminf(x, __shfl_xor_sync(0xffffffffu, x, 2));
            if ((lane & 3) == 0 && m < MC) {
                int b = b0 + cb + j0 + jj;
                out[(size_t)b * (NCLS + 1) + grp] =
                    expf(-(__ldg(&g_fsq[b]) + x) * INV_SIGMA);
            }
        }
    }
    TC_FENCE_BEFORE();
    __syncthreads();
    if (wid == 0) TC_DEALLOC(tmem, 128);
#else
    int tid = threadIdx.x;
    int m0 = (int)blockIdx.x * 128, b0 = (int)blockIdx.y * 128;
    int m = m0 + (tid & 127);
    if (m >= MC || tid >= 128) return;
    float a = g_a[m];
    int grp = m >> 2;
    const float* wrow = W + (size_t)m * HID;
    for (int jb = 0; jb < 128; jb++) {
        int b = b0 + jb;
        const float* frow = F + (size_t)b * HID;
        float dot = 0.f;
        for (int k = 0; k < HID; k++) dot = fmaf(wrow[k], frow[k], dot);
        float x = fmaf(-2.f, dot, a);
        x = fminf(x, __shfl_xor_sync(0xffffffffu, x, 1));
        x = fminf(x, __shfl_xor_sync(0xffffffffu, x, 2));
        if ((tid & 3) == 0)
            out[(size_t)b * (NCLS + 1) + grp] =
                expf(-(g_fsq[b] + x) * INV_SIGMA);
    }
#endif
}

// ---------------- f2 + fused finalize (last-arriving block) ----------------
__global__ void __launch_bounds__(256) k_f2fin(float* __restrict__ out) {
    __shared__ double sd[8], sd2[8], sd3[8], sd4[8], sd5[8];
    __shared__ bool is_last;
    __shared__ float rw_s;
    int tid = threadIdx.x, wid = tid >> 5, lane = tid & 31;

    double acc = 0.0;
    for (int i = (int)blockIdx.x * 256 + tid; i < 10 * 16384; i += 160 * 256) {
        int t = i >> 14, e = i & 16383;
        float g = 0.f;
        #pragma unroll
        for (int z = 0; z < 10; z++) g += g_G2[((size_t)(t * 10 + z) << 14) + e];
        double w = (c_ti[t] == c_tj[t]) ? 1.0 : 2.0;
        acc += w * (double)g * (double)g;
    }
    #pragma unroll
    for (int o = 16; o > 0; o >>= 1)
        acc += __shfl_down_sync(0xffffffffu, acc, o);
    if (lane == 0) sd[wid] = acc;
    __syncthreads();
    if (tid == 0) {
        double f = 0.0;
        #pragma unroll
        for (int j = 0; j < 8; j++) f += sd[j];
        g_f2p[blockIdx.x] = f;
    }
    __threadfence();
    __syncthreads();
    if (tid == 0) {
        unsigned v = atomicAdd(&g_ctr, 1u);
        is_last = (v == 159u);
    }
    __syncthreads();
    if (!is_last) return;
    if (tid == 0) g_ctr = 0;
    __threadfence();

    double la  = (tid < 141) ? g_ap[tid]  : 0.0;
    double la2 = (tid < 141) ? g_a2p[tid] : 0.0;
    double ls2 = (tid < 128) ? g_s2p[tid] : 0.0;
    double lus = (tid < 128) ? g_usp[tid] : 0.0;
    double lf2 = (tid < 160) ? g_f2p[tid] : 0.0;
    #pragma unroll
    for (int o = 16; o > 0; o >>= 1) {
        la  += __shfl_down_sync(0xffffffffu, la,  o);
        la2 += __shfl_down_sync(0xffffffffu, la2, o);
        ls2 += __shfl_down_sync(0xffffffffu, ls2, o);
        lus += __shfl_down_sync(0xffffffffu, lus, o);
        lf2 += __shfl_down_sync(0xffffffffu, lf2, o);
    }
    if (lane == 0) { sd[wid]=la; sd2[wid]=la2; sd3[wid]=ls2; sd4[wid]=lus; sd5[wid]=lf2; }
    __syncthreads();
    if (tid == 0) {
        double sum_a=0, sum_a2=0, s2=0, sum_at=0, F2=0;
        #pragma unroll
        for (int j = 0; j < 8; j++) {
            sum_a += sd[j]; sum_a2 += sd2[j]; s2 += sd3[j];
            sum_at += sd4[j]; F2 += sd5[j];
        }
        double mc = (double)MC;
        double denom = 2.0 / (mc * mc - mc);
        double S1 = mc * sum_a - s2;
        double mu = denom * S1;
        double S2 = mc * sum_a2 + sum_a * sum_a + 2.0 * F2 - 4.0 * sum_at;
        rw_s = (float)(denom * S2 - mu * mu);
    }
    __syncthreads();
    #pragma unroll
    for (int j = 0; j < 2; j++)
        out[(size_t)(tid * 2 + j) * (NCLS + 1) + NCLS] = rw_s;
}

extern "C" void kernel_launch(void* const* d_in, const int* in_sizes, int n_in,
                              void* d_out, int out_size) {
    const float* F = (const float*)d_in[0];   // [512,512]
    const float* W = (const float*)d_in[1];   // [4000,512]
    float* out = (float*)d_out;               // [512,1001]
    (void)in_sizes; (void)n_in; (void)out_size;

    static bool inited = false;
    static cudaStream_t s1, s2;
    static cudaEvent_t evA, evT, evP, evS, evB;
    if (!inited) {
        cudaFuncSetAttribute(k_fw_tc, cudaFuncAttributeMaxDynamicSharedMemorySize,
                             SMEM_TC);
        cudaFuncSetAttribute(k_gram_tc, cudaFuncAttributeMaxDynamicSharedMemorySize,
                             SMEM_TC);
        cudaStreamCreateWithFlags(&s1, cudaStreamNonBlocking);
        cudaStreamCreateWithFlags(&s2, cudaStreamNonBlocking);
        cudaEventCreateWithFlags(&evA, cudaEventDisableTiming);
        cudaEventCreateWithFlags(&evT, cudaEventDisableTiming);
        cudaEventCreateWithFlags(&evP, cudaEventDisableTiming);
        cudaEventCreateWithFlags(&evS, cudaEventDisableTiming);
        cudaEventCreateWithFlags(&evB, cudaEventDisableTiming);
        inited = true;
    }

    // fork
    cudaEventRecord(evA, 0);
    cudaStreamWaitEvent(s1, evA, 0);

    // chain 0 (default): transpose -> gram
    k_transpose<<<2000, 256>>>(W);
    cudaEventRecord(evT, 0);                  // Wt ready
    k_gram_tc<<<100, 256, SMEM_TC>>>();

    // chain 1 (s1): pre -> fw
    k_pre<<<141, 256, 0, s1>>>(W, F);
    cudaEventRecord(evP, s1);
    k_fw_tc<<<dim3(32, 4), 256, SMEM_TC, s1>>>(F, W, out);
    cudaEventRecord(evB, s1);

    // chain 2 (s2): su (needs Wt + a) — off the critical path
    cudaStreamWaitEvent(s2, evT, 0);
    cudaStreamWaitEvent(s2, evP, 0);
    k_su<<<128, 256, 0, s2>>>();
    cudaEventRecord(evS, s2);

    // join: f2 + fused finalize
    cudaStreamWaitEvent(0, evB, 0);
    cudaStreamWaitEvent(0, evS, 0);
    k_f2fin<<<160, 256>>>(out);
}